// round 2
// baseline (speedup 1.0000x reference)
#include <cuda_runtime.h>
#include <math.h>
#include <stdint.h>

// Problem constants
#define T_SEQ 2048
#define B_SZ  4
#define EMB   1024
#define NHEADS 16
#define HD    64
#define FFN_DIM 4096
#define MTOK  (T_SEQ * B_SZ)   // 8192 tokens

// ---------------- scratch (device globals; no cudaMalloc allowed) ----------
__device__ float g_X0[MTOK * EMB];      // state transposed to (B,T,E) token-major
__device__ float g_Q [MTOK * EMB];
__device__ float g_K [MTOK * EMB];
__device__ float g_V [MTOK * EMB];
__device__ float g_ATTN[MTOK * EMB];
__device__ float g_Y [MTOK * EMB];      // GEMM epilogue temp (reused)
__device__ float g_X1[MTOK * EMB];      // post-LN1 activations / FFN residual
__device__ float g_H [MTOK * FFN_DIM];  // FFN hidden

// ---------------------------------------------------------------------------
// Transpose (T,B,E) -> (B,T,E) token-major, vectorized float4
// ---------------------------------------------------------------------------
__global__ __launch_bounds__(256) void transpose_in_kernel(const float* __restrict__ state)
{
    // one block per token row; 256 threads x float4 = 1024 floats
    int m = blockIdx.x;               // m = b*T + t
    int b = m / T_SEQ;
    int t = m % T_SEQ;
    const float4* src = (const float4*)(state + (size_t)t * B_SZ * EMB + (size_t)b * EMB);
    float4* dst = (float4*)(g_X0 + (size_t)m * EMB);
    dst[threadIdx.x] = src[threadIdx.x];
}

// ---------------------------------------------------------------------------
// SGEMM: C[m,n] = sum_k A[m,k] * W[n,k] + bias[n]  (+ epilogue)
//   A: MxK row-major, W: NxK row-major (i.e. x @ W^T)
//   mode 0: plain   mode 2: relu   mode 3: + res[m*N + n]
//   BM=BN=128, BK=16, 256 threads, 8x8 per thread (strided mapping)
// ---------------------------------------------------------------------------
__global__ __launch_bounds__(256) void sgemm_kernel(
    const float* __restrict__ A, const float* __restrict__ W,
    const float* __restrict__ bias, const float* __restrict__ res,
    float* __restrict__ C, int M, int N, int K, int mode)
{
    __shared__ float As[16][128];
    __shared__ float Bs[16][128];

    const int tid = threadIdx.x;
    const int ty = tid >> 4;        // 0..15
    const int tx = tid & 15;        // 0..15
    const int m0 = blockIdx.y * 128;
    const int n0 = blockIdx.x * 128;

    // load mapping: each thread loads one row's 8 contiguous K elements (2x float4)
    const int lm = tid >> 1;          // 0..127
    const int lk = (tid & 1) * 8;     // 0 or 8

    float acc[8][8];
#pragma unroll
    for (int i = 0; i < 8; i++)
#pragma unroll
        for (int j = 0; j < 8; j++) acc[i][j] = 0.f;

    const float* Ap = A + (size_t)(m0 + lm) * K + lk;
    const float* Wp = W + (size_t)(n0 + lm) * K + lk;

    for (int k0 = 0; k0 < K; k0 += 16) {
        float4 a0 = *(const float4*)(Ap + k0);
        float4 a1 = *(const float4*)(Ap + k0 + 4);
        float4 b0 = *(const float4*)(Wp + k0);
        float4 b1 = *(const float4*)(Wp + k0 + 4);
        __syncthreads();
        As[lk + 0][lm] = a0.x; As[lk + 1][lm] = a0.y; As[lk + 2][lm] = a0.z; As[lk + 3][lm] = a0.w;
        As[lk + 4][lm] = a1.x; As[lk + 5][lm] = a1.y; As[lk + 6][lm] = a1.z; As[lk + 7][lm] = a1.w;
        Bs[lk + 0][lm] = b0.x; Bs[lk + 1][lm] = b0.y; Bs[lk + 2][lm] = b0.z; Bs[lk + 3][lm] = b0.w;
        Bs[lk + 4][lm] = b1.x; Bs[lk + 5][lm] = b1.y; Bs[lk + 6][lm] = b1.z; Bs[lk + 7][lm] = b1.w;
        __syncthreads();
#pragma unroll
        for (int k = 0; k < 16; k++) {
            float a[8], b[8];
#pragma unroll
            for (int i = 0; i < 8; i++) a[i] = As[k][ty + 16 * i];
#pragma unroll
            for (int j = 0; j < 8; j++) b[j] = Bs[k][tx + 16 * j];
#pragma unroll
            for (int i = 0; i < 8; i++)
#pragma unroll
                for (int j = 0; j < 8; j++) acc[i][j] += a[i] * b[j];
        }
    }

#pragma unroll
    for (int i = 0; i < 8; i++) {
        int m = m0 + ty + 16 * i;
#pragma unroll
        for (int j = 0; j < 8; j++) {
            int n = n0 + tx + 16 * j;
            float v = acc[i][j] + bias[n];
            if (mode == 2) v = fmaxf(v, 0.f);
            else if (mode == 3) v += res[(size_t)m * N + n];
            C[(size_t)m * N + n] = v;
        }
    }
}

// ---------------------------------------------------------------------------
// Flash-attention (fp32, streaming softmax).
//   grid.x = T/128 (query tiles), grid.y = B*H
//   BM=128 query rows, BN=64 key rows per iteration, 256 threads
// ---------------------------------------------------------------------------
#define ATTN_SMEM_FLOATS (128*65 + 64*65 + 64*64 + 128*68)

__global__ __launch_bounds__(256) void attn_kernel(const uint8_t* __restrict__ mask)
{
    extern __shared__ float sm[];
    float* Qs = sm;                      // [128][65]
    float* Ks = Qs + 128 * 65;           // [64][65]
    float* Vs = Ks + 64 * 65;            // [64][64]
    float* Ps = Vs + 64 * 64;            // [128][68]

    const int tq = blockIdx.x * 128;
    const int bh = blockIdx.y;
    const int b = bh >> 4;
    const int h = bh & 15;
    const int tid = threadIdx.x;
    const int ty = tid >> 4;
    const int tx = tid & 15;

    // load Q tile: 128 rows x 64 dims
    {
        const float* Qg = g_Q + ((size_t)(b * T_SEQ + tq)) * EMB + h * HD;
        for (int it = tid; it < 128 * 16; it += 256) {
            int r = it >> 4, c4 = (it & 15) * 4;
            float4 v = *(const float4*)(Qg + (size_t)r * EMB + c4);
            Qs[r * 65 + c4 + 0] = v.x; Qs[r * 65 + c4 + 1] = v.y;
            Qs[r * 65 + c4 + 2] = v.z; Qs[r * 65 + c4 + 3] = v.w;
        }
    }

    float mrow[8], lrow[8], O[8][4];
#pragma unroll
    for (int i = 0; i < 8; i++) {
        mrow[i] = -1e30f; lrow[i] = 0.f;
#pragma unroll
        for (int j = 0; j < 4; j++) O[i][j] = 0.f;
    }

    const uint8_t* mb = mask + (size_t)b * T_SEQ;

    for (int kt = 0; kt < T_SEQ; kt += 64) {
        __syncthreads();   // WAR: previous PV done before overwriting K/V
        const float* Kg = g_K + ((size_t)(b * T_SEQ + kt)) * EMB + h * HD;
        const float* Vg = g_V + ((size_t)(b * T_SEQ + kt)) * EMB + h * HD;
        for (int it = tid; it < 64 * 16; it += 256) {
            int r = it >> 4, c4 = (it & 15) * 4;
            float4 kv = *(const float4*)(Kg + (size_t)r * EMB + c4);
            Ks[r * 65 + c4 + 0] = kv.x; Ks[r * 65 + c4 + 1] = kv.y;
            Ks[r * 65 + c4 + 2] = kv.z; Ks[r * 65 + c4 + 3] = kv.w;
            float4 vv = *(const float4*)(Vg + (size_t)r * EMB + c4);
            Vs[r * 64 + c4 + 0] = vv.x; Vs[r * 64 + c4 + 1] = vv.y;
            Vs[r * 64 + c4 + 2] = vv.z; Vs[r * 64 + c4 + 3] = vv.w;
        }
        __syncthreads();

        // S = Q K^T  (thread owns rows ty+16i, cols tx+16j)
        float s[8][4];
#pragma unroll
        for (int i = 0; i < 8; i++)
#pragma unroll
            for (int j = 0; j < 4; j++) s[i][j] = 0.f;

#pragma unroll 8
        for (int d = 0; d < 64; d++) {
            float a[8], kb[4];
#pragma unroll
            for (int i = 0; i < 8; i++) a[i] = Qs[(ty + 16 * i) * 65 + d];
#pragma unroll
            for (int j = 0; j < 4; j++) kb[j] = Ks[(tx + 16 * j) * 65 + d];
#pragma unroll
            for (int i = 0; i < 8; i++)
#pragma unroll
                for (int j = 0; j < 4; j++) s[i][j] += a[i] * kb[j];
        }

        // scale + mask
        bool mk[4];
#pragma unroll
        for (int j = 0; j < 4; j++) mk[j] = (mb[kt + tx + 16 * j] != 0);
#pragma unroll
        for (int i = 0; i < 8; i++)
#pragma unroll
            for (int j = 0; j < 4; j++)
                s[i][j] = mk[j] ? -1e30f : s[i][j] * 0.125f;  // 1/sqrt(64)

        // online softmax per row
#pragma unroll
        for (int i = 0; i < 8; i++) {
            float mx = s[i][0];
#pragma unroll
            for (int j = 1; j < 4; j++) mx = fmaxf(mx, s[i][j]);
#pragma unroll
            for (int off = 8; off >= 1; off >>= 1)
                mx = fmaxf(mx, __shfl_xor_sync(0xffffffffu, mx, off, 16));
            float mn = fmaxf(mrow[i], mx);
            float alpha = __expf(mrow[i] - mn);
            mrow[i] = mn;
            float rs = 0.f;
#pragma unroll
            for (int j = 0; j < 4; j++) {
                float p = __expf(s[i][j] - mn);
                Ps[(ty + 16 * i) * 68 + tx + 16 * j] = p;
                rs += p;
            }
#pragma unroll
            for (int off = 8; off >= 1; off >>= 1)
                rs += __shfl_xor_sync(0xffffffffu, rs, off, 16);
            lrow[i] = lrow[i] * alpha + rs;
#pragma unroll
            for (int j = 0; j < 4; j++) O[i][j] *= alpha;
        }
        __syncthreads();   // Ps visible to all

        // O += P @ V  (thread owns rows ty+16i, output cols tx+16j of 64)
#pragma unroll 8
        for (int k = 0; k < 64; k++) {
            float pv[8], vv[4];
#pragma unroll
            for (int i = 0; i < 8; i++) pv[i] = Ps[(ty + 16 * i) * 68 + k];
#pragma unroll
            for (int j = 0; j < 4; j++) vv[j] = Vs[k * 64 + tx + 16 * j];
#pragma unroll
            for (int i = 0; i < 8; i++)
#pragma unroll
                for (int j = 0; j < 4; j++) O[i][j] += pv[i] * vv[j];
        }
    }

    // write out: ATTN[(b*T + tq + r), h*64 + c]
#pragma unroll
    for (int i = 0; i < 8; i++) {
        float inv = 1.f / lrow[i];
        int r = tq + ty + 16 * i;
        float* dst = g_ATTN + ((size_t)(b * T_SEQ + r)) * EMB + h * HD;
#pragma unroll
        for (int j = 0; j < 4; j++) dst[tx + 16 * j] = O[i][j] * inv;
    }
}

// ---------------------------------------------------------------------------
// LayerNorm over last dim (1024). One block per token row.
//   transposed=0: out[m*E + c]; transposed=1: out[t*B*E + b*E + c]
// ---------------------------------------------------------------------------
__global__ __launch_bounds__(256) void ln_kernel(
    const float* __restrict__ X, const float* __restrict__ gw,
    const float* __restrict__ bw, float* __restrict__ out, int transposed)
{
    int m = blockIdx.x;
    float4 v = ((const float4*)(X + (size_t)m * EMB))[threadIdx.x];
    float s = v.x + v.y + v.z + v.w;
    float sq = v.x * v.x + v.y * v.y + v.z * v.z + v.w * v.w;

    __shared__ float rs[256], rq[256];
    rs[threadIdx.x] = s; rq[threadIdx.x] = sq;
    __syncthreads();
    for (int st = 128; st > 0; st >>= 1) {
        if (threadIdx.x < st) {
            rs[threadIdx.x] += rs[threadIdx.x + st];
            rq[threadIdx.x] += rq[threadIdx.x + st];
        }
        __syncthreads();
    }
    float mu  = rs[0] * (1.f / EMB);
    float var = rq[0] * (1.f / EMB) - mu * mu;
    float inv = rsqrtf(var + 1e-5f);

    float4 g4 = ((const float4*)gw)[threadIdx.x];
    float4 b4 = ((const float4*)bw)[threadIdx.x];
    float4 o;
    o.x = (v.x - mu) * inv * g4.x + b4.x;
    o.y = (v.y - mu) * inv * g4.y + b4.y;
    o.z = (v.z - mu) * inv * g4.z + b4.z;
    o.w = (v.w - mu) * inv * g4.w + b4.w;

    size_t obase;
    if (transposed) {
        int b = m / T_SEQ, t = m % T_SEQ;
        obase = (size_t)t * B_SZ * EMB + (size_t)b * EMB;
    } else {
        obase = (size_t)m * EMB;
    }
    ((float4*)(out + obase))[threadIdx.x] = o;
}

// ---------------------------------------------------------------------------
extern "C" void kernel_launch(void* const* d_in, const int* in_sizes, int n_in,
                              void* d_out, int out_size)
{
    const float*   state = (const float*)d_in[0];
    const uint8_t* mask  = (const uint8_t*)d_in[1];
    const float* q_w  = (const float*)d_in[2];
    const float* q_b  = (const float*)d_in[3];
    const float* k_w  = (const float*)d_in[4];
    const float* k_b  = (const float*)d_in[5];
    const float* v_w  = (const float*)d_in[6];
    const float* v_b  = (const float*)d_in[7];
    const float* out_w = (const float*)d_in[8];
    const float* out_b = (const float*)d_in[9];
    const float* ln1_g = (const float*)d_in[10];
    const float* ln1_b = (const float*)d_in[11];
    const float* fc1_w = (const float*)d_in[12];
    const float* fc1_b = (const float*)d_in[13];
    const float* fc2_w = (const float*)d_in[14];
    const float* fc2_b = (const float*)d_in[15];
    const float* ln2_g = (const float*)d_in[16];
    const float* ln2_b = (const float*)d_in[17];
    float* out = (float*)d_out;

    float *pX0, *pQ, *pK, *pV, *pATTN, *pY, *pX1, *pH;
    cudaGetSymbolAddress((void**)&pX0,   g_X0);
    cudaGetSymbolAddress((void**)&pQ,    g_Q);
    cudaGetSymbolAddress((void**)&pK,    g_K);
    cudaGetSymbolAddress((void**)&pV,    g_V);
    cudaGetSymbolAddress((void**)&pATTN, g_ATTN);
    cudaGetSymbolAddress((void**)&pY,    g_Y);
    cudaGetSymbolAddress((void**)&pX1,   g_X1);
    cudaGetSymbolAddress((void**)&pH,    g_H);

    const size_t attn_smem = (size_t)ATTN_SMEM_FLOATS * sizeof(float);
    cudaFuncSetAttribute(attn_kernel, cudaFuncAttributeMaxDynamicSharedMemorySize,
                         (int)attn_smem);

    // 1. transpose (T,B,E) -> token-major (B,T,E)
    transpose_in_kernel<<<MTOK, 256>>>(state);

    // 2. QKV projections
    dim3 gProj(EMB / 128, MTOK / 128);
    sgemm_kernel<<<gProj, 256>>>(pX0, q_w, q_b, nullptr, pQ, MTOK, EMB, EMB, 0);
    sgemm_kernel<<<gProj, 256>>>(pX0, k_w, k_b, nullptr, pK, MTOK, EMB, EMB, 0);
    sgemm_kernel<<<gProj, 256>>>(pX0, v_w, v_b, nullptr, pV, MTOK, EMB, EMB, 0);

    // 3. attention
    dim3 gAttn(T_SEQ / 128, B_SZ * NHEADS);
    attn_kernel<<<gAttn, 256, attn_smem>>>(mask);

    // 4. out projection + residual(state)
    sgemm_kernel<<<gProj, 256>>>(pATTN, out_w, out_b, pX0, pY, MTOK, EMB, EMB, 3);

    // 5. LN1 -> X1
    ln_kernel<<<MTOK, 256>>>(pY, ln1_g, ln1_b, pX1, 0);

    // 6. FFN fc1 + relu
    dim3 gFc1(FFN_DIM / 128, MTOK / 128);
    sgemm_kernel<<<gFc1, 256>>>(pX1, fc1_w, fc1_b, nullptr, pH, MTOK, FFN_DIM, EMB, 2);

    // 7. FFN fc2 + residual(X1)
    sgemm_kernel<<<gProj, 256>>>(pH, fc2_w, fc2_b, pX1, pY, MTOK, EMB, FFN_DIM, 3);

    // 8. LN2 -> output in (T,B,E) layout
    ln_kernel<<<MTOK, 256>>>(pY, ln2_g, ln2_b, out, 1);
}

// round 4
// speedup vs baseline: 2.0450x; 2.0450x over previous
#include <cuda_runtime.h>
#include <math.h>
#include <stdint.h>

// Problem constants
#define T_SEQ 2048
#define B_SZ  4
#define EMB   1024
#define NHEADS 16
#define HD    64
#define FFN_DIM 4096
#define MTOK  (T_SEQ * B_SZ)   // 8192 tokens

// ---------------- scratch (device globals; no cudaMalloc allowed) ----------
__device__ float g_X0[MTOK * EMB];
__device__ float g_Q [MTOK * EMB];
__device__ float g_K [MTOK * EMB];
__device__ float g_V [MTOK * EMB];
__device__ float g_ATTN[MTOK * EMB];
__device__ float g_Y [MTOK * EMB];
__device__ float g_X1[MTOK * EMB];
__device__ float g_H [MTOK * FFN_DIM];

// ---------------------------------------------------------------------------
__device__ __forceinline__ uint32_t f2tf32(float f) {
    uint32_t r;
    asm("cvt.rna.tf32.f32 %0, %1;" : "=r"(r) : "f"(f));
    return r;
}
__device__ __forceinline__ void mma_tf32(float* d, const uint32_t* a, const uint32_t* b) {
    asm volatile(
        "mma.sync.aligned.m16n8k8.row.col.f32.tf32.tf32.f32 "
        "{%0,%1,%2,%3}, {%4,%5,%6,%7}, {%8,%9}, {%0,%1,%2,%3};"
        : "+f"(d[0]), "+f"(d[1]), "+f"(d[2]), "+f"(d[3])
        : "r"(a[0]), "r"(a[1]), "r"(a[2]), "r"(a[3]), "r"(b[0]), "r"(b[1]));
}

// ---------------------------------------------------------------------------
// Tensor-core GEMM via mma.sync tf32.
//   C[m,n] = sum_k A[m,k] * W[n,k] + bias[n] (+epilogue)
//   CTA tile 128x128, BK=32, 256 thr = 8 warps (2m x 4n), warp tile 64x32.
//   mode 0: plain   mode 2: relu   mode 3: + res
// SMEM per buffer: A[128][36] + B[128][36] floats (pad 36 -> conflict-free)
// ---------------------------------------------------------------------------
#define LDS_PAD 36
#define GEMM_BUF_FLOATS (128 * LDS_PAD)
#define GEMM_SMEM_BYTES (4 * GEMM_BUF_FLOATS * 4)   // A0,B0,A1,B1

__global__ __launch_bounds__(256, 2) void gemm_tc_kernel(
    const float* __restrict__ A, const float* __restrict__ W,
    const float* __restrict__ bias, const float* __restrict__ res,
    float* __restrict__ C, int M, int N, int K, int mode)
{
    extern __shared__ uint32_t smg[];
    uint32_t* As[2] = { smg,                      smg + 2 * GEMM_BUF_FLOATS };
    uint32_t* Bs[2] = { smg + GEMM_BUF_FLOATS,    smg + 3 * GEMM_BUF_FLOATS };

    const int tid = threadIdx.x;
    const int wid = tid >> 5;
    const int lane = tid & 31;
    const int g   = lane >> 2;   // 0..7
    const int tig = lane & 3;    // 0..3
    const int wm = wid >> 2;     // 0..1
    const int wn = wid & 3;      // 0..3
    const int m0 = blockIdx.y * 128;
    const int n0 = blockIdx.x * 128;

    const float* Ap = A + (size_t)m0 * K;
    const float* Wp = W + (size_t)n0 * K;

    // load mapping: idx = tid + 256*i -> row = idx/8, c = (idx%8)*4
    const int lrow = tid >> 1;              // not used; use idx form below

    float acc[4][4][4];
#pragma unroll
    for (int mt = 0; mt < 4; mt++)
#pragma unroll
        for (int nt = 0; nt < 4; nt++)
#pragma unroll
            for (int e = 0; e < 4; e++) acc[mt][nt][e] = 0.f;

    const int S = K >> 5;

    // prologue: stage 0
    {
#pragma unroll
        for (int i = 0; i < 4; i++) {
            int idx = tid + 256 * i;
            int row = idx >> 3, c = (idx & 7) << 2;
            float4 va = *(const float4*)(Ap + (size_t)row * K + c);
            float4 vb = *(const float4*)(Wp + (size_t)row * K + c);
            uint32_t* da = As[0] + row * LDS_PAD + c;
            uint32_t* db = Bs[0] + row * LDS_PAD + c;
            *(uint4*)da = make_uint4(f2tf32(va.x), f2tf32(va.y), f2tf32(va.z), f2tf32(va.w));
            *(uint4*)db = make_uint4(f2tf32(vb.x), f2tf32(vb.y), f2tf32(vb.z), f2tf32(vb.w));
        }
    }
    __syncthreads();

    for (int s = 0; s < S; s++) {
        const int cb = s & 1;
        float4 ra[4], rb[4];
        const bool more = (s + 1 < S);
        if (more) {
            int k0 = (s + 1) << 5;
#pragma unroll
            for (int i = 0; i < 4; i++) {
                int idx = tid + 256 * i;
                int row = idx >> 3, c = (idx & 7) << 2;
                ra[i] = *(const float4*)(Ap + (size_t)row * K + k0 + c);
                rb[i] = *(const float4*)(Wp + (size_t)row * K + k0 + c);
            }
        }

        // compute on buffer cb: 4 k-steps of 8
        const uint32_t* Ab = As[cb] + (wm * 64) * LDS_PAD;
        const uint32_t* Bb = Bs[cb] + (wn * 32) * LDS_PAD;
#pragma unroll
        for (int ks = 0; ks < 4; ks++) {
            uint32_t bf[4][2];
#pragma unroll
            for (int nt = 0; nt < 4; nt++) {
                const uint32_t* bp = Bb + (nt * 8 + g) * LDS_PAD + ks * 8 + tig;
                bf[nt][0] = bp[0];
                bf[nt][1] = bp[4];
            }
#pragma unroll
            for (int mt = 0; mt < 4; mt++) {
                uint32_t af[4];
                const uint32_t* ap = Ab + (mt * 16 + g) * LDS_PAD + ks * 8 + tig;
                af[0] = ap[0];
                af[1] = ap[8 * LDS_PAD];
                af[2] = ap[4];
                af[3] = ap[8 * LDS_PAD + 4];
#pragma unroll
                for (int nt = 0; nt < 4; nt++)
                    mma_tf32(acc[mt][nt], af, bf[nt]);
            }
        }

        if (more) {
            __syncthreads();   // everyone done computing next buffer's prior contents
            const int nb = (s + 1) & 1;
#pragma unroll
            for (int i = 0; i < 4; i++) {
                int idx = tid + 256 * i;
                int row = idx >> 3, c = (idx & 7) << 2;
                uint32_t* da = As[nb] + row * LDS_PAD + c;
                uint32_t* db = Bs[nb] + row * LDS_PAD + c;
                *(uint4*)da = make_uint4(f2tf32(ra[i].x), f2tf32(ra[i].y), f2tf32(ra[i].z), f2tf32(ra[i].w));
                *(uint4*)db = make_uint4(f2tf32(rb[i].x), f2tf32(rb[i].y), f2tf32(rb[i].z), f2tf32(rb[i].w));
            }
            __syncthreads();
        }
    }

    // epilogue: c0/c1 at (row, 2*tig), c2/c3 at (row+8, 2*tig)
#pragma unroll
    for (int mt = 0; mt < 4; mt++) {
        int r0 = m0 + wm * 64 + mt * 16 + g;
#pragma unroll
        for (int half = 0; half < 2; half++) {
            int m = r0 + half * 8;
            float* Crow = C + (size_t)m * N + n0;
            const float* Rrow = res + (size_t)m * N + n0;
#pragma unroll
            for (int nt = 0; nt < 4; nt++) {
                int n = wn * 32 + nt * 8 + tig * 2;
                float2 o;
                o.x = acc[mt][nt][half * 2 + 0] + bias[n0 + n + 0];
                o.y = acc[mt][nt][half * 2 + 1] + bias[n0 + n + 1];
                if (mode == 2) {
                    o.x = fmaxf(o.x, 0.f); o.y = fmaxf(o.y, 0.f);
                } else if (mode == 3) {
                    float2 rr = *(const float2*)(Rrow + n);
                    o.x += rr.x; o.y += rr.y;
                }
                *(float2*)(Crow + n) = o;
            }
        }
    }
}

// ---------------------------------------------------------------------------
// Transpose (T,B,E) -> (B,T,E) token-major
// ---------------------------------------------------------------------------
__global__ __launch_bounds__(256) void transpose_in_kernel(const float* __restrict__ state)
{
    int m = blockIdx.x;
    int b = m / T_SEQ;
    int t = m % T_SEQ;
    const float4* src = (const float4*)(state + (size_t)t * B_SZ * EMB + (size_t)b * EMB);
    float4* dst = (float4*)(g_X0 + (size_t)m * EMB);
    dst[threadIdx.x] = src[threadIdx.x];
}

// ---------------------------------------------------------------------------
// Flash-attention (fp32 SIMT, streaming softmax).
// ---------------------------------------------------------------------------
#define ATTN_SMEM_FLOATS (128*65 + 64*65 + 64*64 + 128*68)

__global__ __launch_bounds__(256) void attn_kernel(const uint8_t* __restrict__ mask)
{
    extern __shared__ float smf[];
    float* Qs = smf;
    float* Ks = Qs + 128 * 65;
    float* Vs = Ks + 64 * 65;
    float* Ps = Vs + 64 * 64;

    const int tq = blockIdx.x * 128;
    const int bh = blockIdx.y;
    const int b = bh >> 4;
    const int h = bh & 15;
    const int tid = threadIdx.x;
    const int ty = tid >> 4;
    const int tx = tid & 15;

    {
        const float* Qg = g_Q + ((size_t)(b * T_SEQ + tq)) * EMB + h * HD;
        for (int it = tid; it < 128 * 16; it += 256) {
            int r = it >> 4, c4 = (it & 15) * 4;
            float4 v = *(const float4*)(Qg + (size_t)r * EMB + c4);
            Qs[r * 65 + c4 + 0] = v.x; Qs[r * 65 + c4 + 1] = v.y;
            Qs[r * 65 + c4 + 2] = v.z; Qs[r * 65 + c4 + 3] = v.w;
        }
    }

    float mrow[8], lrow[8], O[8][4];
#pragma unroll
    for (int i = 0; i < 8; i++) {
        mrow[i] = -1e30f; lrow[i] = 0.f;
#pragma unroll
        for (int j = 0; j < 4; j++) O[i][j] = 0.f;
    }

    const uint8_t* mb = mask + (size_t)b * T_SEQ;

    for (int kt = 0; kt < T_SEQ; kt += 64) {
        __syncthreads();
        const float* Kg = g_K + ((size_t)(b * T_SEQ + kt)) * EMB + h * HD;
        const float* Vg = g_V + ((size_t)(b * T_SEQ + kt)) * EMB + h * HD;
        for (int it = tid; it < 64 * 16; it += 256) {
            int r = it >> 4, c4 = (it & 15) * 4;
            float4 kv = *(const float4*)(Kg + (size_t)r * EMB + c4);
            Ks[r * 65 + c4 + 0] = kv.x; Ks[r * 65 + c4 + 1] = kv.y;
            Ks[r * 65 + c4 + 2] = kv.z; Ks[r * 65 + c4 + 3] = kv.w;
            float4 vv = *(const float4*)(Vg + (size_t)r * EMB + c4);
            Vs[r * 64 + c4 + 0] = vv.x; Vs[r * 64 + c4 + 1] = vv.y;
            Vs[r * 64 + c4 + 2] = vv.z; Vs[r * 64 + c4 + 3] = vv.w;
        }
        __syncthreads();

        float s[8][4];
#pragma unroll
        for (int i = 0; i < 8; i++)
#pragma unroll
            for (int j = 0; j < 4; j++) s[i][j] = 0.f;

#pragma unroll 8
        for (int d = 0; d < 64; d++) {
            float a[8], kb[4];
#pragma unroll
            for (int i = 0; i < 8; i++) a[i] = Qs[(ty + 16 * i) * 65 + d];
#pragma unroll
            for (int j = 0; j < 4; j++) kb[j] = Ks[(tx + 16 * j) * 65 + d];
#pragma unroll
            for (int i = 0; i < 8; i++)
#pragma unroll
                for (int j = 0; j < 4; j++) s[i][j] += a[i] * kb[j];
        }

        bool mk[4];
#pragma unroll
        for (int j = 0; j < 4; j++) mk[j] = (mb[kt + tx + 16 * j] != 0);
#pragma unroll
        for (int i = 0; i < 8; i++)
#pragma unroll
            for (int j = 0; j < 4; j++)
                s[i][j] = mk[j] ? -1e30f : s[i][j] * 0.125f;

#pragma unroll
        for (int i = 0; i < 8; i++) {
            float mx = s[i][0];
#pragma unroll
            for (int j = 1; j < 4; j++) mx = fmaxf(mx, s[i][j]);
#pragma unroll
            for (int off = 8; off >= 1; off >>= 1)
                mx = fmaxf(mx, __shfl_xor_sync(0xffffffffu, mx, off, 16));
            float mn = fmaxf(mrow[i], mx);
            float alpha = __expf(mrow[i] - mn);
            mrow[i] = mn;
            float rs = 0.f;
#pragma unroll
            for (int j = 0; j < 4; j++) {
                float p = __expf(s[i][j] - mn);
                Ps[(ty + 16 * i) * 68 + tx + 16 * j] = p;
                rs += p;
            }
#pragma unroll
            for (int off = 8; off >= 1; off >>= 1)
                rs += __shfl_xor_sync(0xffffffffu, rs, off, 16);
            lrow[i] = lrow[i] * alpha + rs;
#pragma unroll
            for (int j = 0; j < 4; j++) O[i][j] *= alpha;
        }
        __syncthreads();

#pragma unroll 8
        for (int k = 0; k < 64; k++) {
            float pv[8], vv[4];
#pragma unroll
            for (int i = 0; i < 8; i++) pv[i] = Ps[(ty + 16 * i) * 68 + k];
#pragma unroll
            for (int j = 0; j < 4; j++) vv[j] = Vs[k * 64 + tx + 16 * j];
#pragma unroll
            for (int i = 0; i < 8; i++)
#pragma unroll
                for (int j = 0; j < 4; j++) O[i][j] += pv[i] * vv[j];
        }
    }

#pragma unroll
    for (int i = 0; i < 8; i++) {
        float inv = 1.f / lrow[i];
        int r = tq + ty + 16 * i;
        float* dst = g_ATTN + ((size_t)(b * T_SEQ + r)) * EMB + h * HD;
#pragma unroll
        for (int j = 0; j < 4; j++) dst[tx + 16 * j] = O[i][j] * inv;
    }
}

// ---------------------------------------------------------------------------
// LayerNorm (E=1024), one block per token row.
// ---------------------------------------------------------------------------
__global__ __launch_bounds__(256) void ln_kernel(
    const float* __restrict__ X, const float* __restrict__ gw,
    const float* __restrict__ bw, float* __restrict__ out, int transposed)
{
    int m = blockIdx.x;
    float4 v = ((const float4*)(X + (size_t)m * EMB))[threadIdx.x];
    float s = v.x + v.y + v.z + v.w;
    float sq = v.x * v.x + v.y * v.y + v.z * v.z + v.w * v.w;

    __shared__ float rs[256], rq[256];
    rs[threadIdx.x] = s; rq[threadIdx.x] = sq;
    __syncthreads();
    for (int st = 128; st > 0; st >>= 1) {
        if (threadIdx.x < st) {
            rs[threadIdx.x] += rs[threadIdx.x + st];
            rq[threadIdx.x] += rq[threadIdx.x + st];
        }
        __syncthreads();
    }
    float mu  = rs[0] * (1.f / EMB);
    float var = rq[0] * (1.f / EMB) - mu * mu;
    float inv = rsqrtf(var + 1e-5f);

    float4 g4 = ((const float4*)gw)[threadIdx.x];
    float4 b4 = ((const float4*)bw)[threadIdx.x];
    float4 o;
    o.x = (v.x - mu) * inv * g4.x + b4.x;
    o.y = (v.y - mu) * inv * g4.y + b4.y;
    o.z = (v.z - mu) * inv * g4.z + b4.z;
    o.w = (v.w - mu) * inv * g4.w + b4.w;

    size_t obase;
    if (transposed) {
        int b = m / T_SEQ, t = m % T_SEQ;
        obase = (size_t)t * B_SZ * EMB + (size_t)b * EMB;
    } else {
        obase = (size_t)m * EMB;
    }
    ((float4*)(out + obase))[threadIdx.x] = o;
}

// ---------------------------------------------------------------------------
extern "C" void kernel_launch(void* const* d_in, const int* in_sizes, int n_in,
                              void* d_out, int out_size)
{
    const float*   state = (const float*)d_in[0];
    const uint8_t* mask  = (const uint8_t*)d_in[1];
    const float* q_w  = (const float*)d_in[2];
    const float* q_b  = (const float*)d_in[3];
    const float* k_w  = (const float*)d_in[4];
    const float* k_b  = (const float*)d_in[5];
    const float* v_w  = (const float*)d_in[6];
    const float* v_b  = (const float*)d_in[7];
    const float* out_w = (const float*)d_in[8];
    const float* out_b = (const float*)d_in[9];
    const float* ln1_g = (const float*)d_in[10];
    const float* ln1_b = (const float*)d_in[11];
    const float* fc1_w = (const float*)d_in[12];
    const float* fc1_b = (const float*)d_in[13];
    const float* fc2_w = (const float*)d_in[14];
    const float* fc2_b = (const float*)d_in[15];
    const float* ln2_g = (const float*)d_in[16];
    const float* ln2_b = (const float*)d_in[17];
    float* out = (float*)d_out;

    float *pX0, *pQ, *pK, *pV, *pATTN, *pY, *pX1, *pH;
    cudaGetSymbolAddress((void**)&pX0,   g_X0);
    cudaGetSymbolAddress((void**)&pQ,    g_Q);
    cudaGetSymbolAddress((void**)&pK,    g_K);
    cudaGetSymbolAddress((void**)&pV,    g_V);
    cudaGetSymbolAddress((void**)&pATTN, g_ATTN);
    cudaGetSymbolAddress((void**)&pY,    g_Y);
    cudaGetSymbolAddress((void**)&pX1,   g_X1);
    cudaGetSymbolAddress((void**)&pH,    g_H);

    const size_t attn_smem = (size_t)ATTN_SMEM_FLOATS * sizeof(float);
    cudaFuncSetAttribute(attn_kernel, cudaFuncAttributeMaxDynamicSharedMemorySize,
                         (int)attn_smem);
    cudaFuncSetAttribute(gemm_tc_kernel, cudaFuncAttributeMaxDynamicSharedMemorySize,
                         GEMM_SMEM_BYTES);

    // 1. transpose (T,B,E) -> token-major
    transpose_in_kernel<<<MTOK, 256>>>(state);

    // 2. QKV projections (tf32 mma.sync)
    dim3 gProj(EMB / 128, MTOK / 128);
    gemm_tc_kernel<<<gProj, 256, GEMM_SMEM_BYTES>>>(pX0, q_w, q_b, nullptr, pQ, MTOK, EMB, EMB, 0);
    gemm_tc_kernel<<<gProj, 256, GEMM_SMEM_BYTES>>>(pX0, k_w, k_b, nullptr, pK, MTOK, EMB, EMB, 0);
    gemm_tc_kernel<<<gProj, 256, GEMM_SMEM_BYTES>>>(pX0, v_w, v_b, nullptr, pV, MTOK, EMB, EMB, 0);

    // 3. attention
    dim3 gAttn(T_SEQ / 128, B_SZ * NHEADS);
    attn_kernel<<<gAttn, 256, attn_smem>>>(mask);

    // 4. out projection + residual(state)
    gemm_tc_kernel<<<gProj, 256, GEMM_SMEM_BYTES>>>(pATTN, out_w, out_b, pX0, pY, MTOK, EMB, EMB, 3);

    // 5. LN1
    ln_kernel<<<MTOK, 256>>>(pY, ln1_g, ln1_b, pX1, 0);

    // 6. FFN fc1 + relu
    dim3 gFc1(FFN_DIM / 128, MTOK / 128);
    gemm_tc_kernel<<<gFc1, 256, GEMM_SMEM_BYTES>>>(pX1, fc1_w, fc1_b, nullptr, pH, MTOK, FFN_DIM, EMB, 2);

    // 7. FFN fc2 + residual(X1)
    gemm_tc_kernel<<<gProj, 256, GEMM_SMEM_BYTES>>>(pH, fc2_w, fc2_b, pX1, pY, MTOK, EMB, FFN_DIM, 3);

    // 8. LN2 -> output (T,B,E)
    ln_kernel<<<MTOK, 256>>>(pY, ln2_g, ln2_b, out, 1);
}

// round 5
// speedup vs baseline: 3.4461x; 1.6851x over previous
#include <cuda_runtime.h>
#include <math.h>
#include <stdint.h>

// Problem constants
#define T_SEQ 2048
#define B_SZ  4
#define EMB   1024
#define NHEADS 16
#define HD    64
#define FFN_DIM 4096
#define MTOK  (T_SEQ * B_SZ)   // 8192 tokens

// ---------------- scratch (device globals; no cudaMalloc allowed) ----------
__device__ float g_X0 [MTOK * EMB];      // exact token-major input
__device__ float g_X0r[MTOK * EMB];      // tf32-rounded copy
__device__ float g_Q  [MTOK * EMB];
__device__ float g_K  [MTOK * EMB];
__device__ float g_V  [MTOK * EMB];
__device__ float g_ATTN[MTOK * EMB];     // rounded attention output
__device__ float g_Y  [MTOK * EMB];
__device__ float g_X1 [MTOK * EMB];      // exact LN1 out
__device__ float g_X1r[MTOK * EMB];      // rounded LN1 out
__device__ float g_H  [MTOK * FFN_DIM];  // rounded relu(fc1)
// rounded weights
__device__ float g_WQr[EMB * EMB];
__device__ float g_WKr[EMB * EMB];
__device__ float g_WVr[EMB * EMB];
__device__ float g_WOr[EMB * EMB];
__device__ float g_W1r[FFN_DIM * EMB];
__device__ float g_W2r[EMB * FFN_DIM];

// ---------------------------------------------------------------------------
__device__ __forceinline__ uint32_t smem_u32(const void* p) {
    uint32_t a;
    asm("{ .reg .u64 t; cvta.to.shared.u64 t, %1; cvt.u32.u64 %0, t; }" : "=r"(a) : "l"(p));
    return a;
}
__device__ __forceinline__ uint32_t f2tf32(float f) {
    uint32_t r;
    asm("cvt.rna.tf32.f32 %0, %1;" : "=r"(r) : "f"(f));
    return r;
}
__device__ __forceinline__ void mma_tf32(float* d, const uint32_t* a, const uint32_t* b) {
    asm volatile(
        "mma.sync.aligned.m16n8k8.row.col.f32.tf32.tf32.f32 "
        "{%0,%1,%2,%3}, {%4,%5,%6,%7}, {%8,%9}, {%0,%1,%2,%3};"
        : "+f"(d[0]), "+f"(d[1]), "+f"(d[2]), "+f"(d[3])
        : "r"(a[0]), "r"(a[1]), "r"(a[2]), "r"(a[3]), "r"(b[0]), "r"(b[1]));
}
__device__ __forceinline__ void cp_async16(uint32_t dst, const void* src) {
    asm volatile("cp.async.cg.shared.global [%0], [%1], 16;" :: "r"(dst), "l"(src));
}
__device__ __forceinline__ void cp_commit() { asm volatile("cp.async.commit_group;"); }
__device__ __forceinline__ void cp_wait0()  { asm volatile("cp.async.wait_group 0;"); }

// ---------------------------------------------------------------------------
// Round fp32 -> tf32-valued fp32 (elementwise, float4)
// ---------------------------------------------------------------------------
__global__ __launch_bounds__(256) void round_tf32_kernel(
    const float* __restrict__ src, float* __restrict__ dst, int n)
{
    int i = (blockIdx.x * 256 + threadIdx.x) * 4;
    if (i < n) {
        float4 v = *(const float4*)(src + i);
        float4 o;
        o.x = __uint_as_float(f2tf32(v.x));
        o.y = __uint_as_float(f2tf32(v.y));
        o.z = __uint_as_float(f2tf32(v.z));
        o.w = __uint_as_float(f2tf32(v.w));
        *(float4*)(dst + i) = o;
    }
}

// ---------------------------------------------------------------------------
// Tensor-core GEMM via mma.sync tf32, cp.async 2-stage pipeline.
//   Inputs A and W must be tf32-valued fp32 already.
//   C[m,n] = sum_k A[m,k]*W[n,k] + bias[n]
//   mode 0: plain   mode 2: relu + round-to-tf32   mode 3: + res
//   CTA 128x128, BK=32, 8 warps (2m x 4n), warp tile 64x32.
// ---------------------------------------------------------------------------
#define LDS_PAD 36
#define GEMM_STAGE_UINTS (128 * LDS_PAD)                 // 4608 per operand
#define GEMM_SMEM_BYTES  (4 * GEMM_STAGE_UINTS * 4)      // A0,B0,A1,B1

__global__ __launch_bounds__(256, 2) void gemm_tc_kernel(
    const float* __restrict__ A, const float* __restrict__ W,
    const float* __restrict__ bias, const float* __restrict__ res,
    float* __restrict__ C, int M, int N, int K, int mode)
{
    extern __shared__ uint32_t smg[];
    const uint32_t sbase = smem_u32(smg);

    const int tid = threadIdx.x;
    const int wid = tid >> 5;
    const int lane = tid & 31;
    const int g   = lane >> 2;
    const int tig = lane & 3;
    const int wm = wid >> 2;
    const int wn = wid & 3;
    const int m0 = blockIdx.y * 128;
    const int n0 = blockIdx.x * 128;

    const float* Ap = A + (size_t)m0 * K;
    const float* Wp = W + (size_t)n0 * K;

    float acc[4][4][4];
#pragma unroll
    for (int mt = 0; mt < 4; mt++)
#pragma unroll
        for (int nt = 0; nt < 4; nt++)
#pragma unroll
            for (int e = 0; e < 4; e++) acc[mt][nt][e] = 0.f;

    const int S = K >> 5;
    const int lrow = tid >> 3;           // 0..31? no: idx-based below
    (void)lrow;

    // issue one stage of cp.async (A and B tiles, 4 chunks each per thread)
    auto issue_stage = [&](int s) {
        const int buf = s & 1;
        const int k0 = s << 5;
        const uint32_t abase = sbase + (uint32_t)(buf * 2 * GEMM_STAGE_UINTS) * 4;
        const uint32_t bbase = abase + GEMM_STAGE_UINTS * 4;
#pragma unroll
        for (int i = 0; i < 4; i++) {
            int idx = tid + 256 * i;
            int row = idx >> 3, c = (idx & 7) << 2;
            uint32_t o = (uint32_t)(row * LDS_PAD + c) * 4;
            cp_async16(abase + o, Ap + (size_t)row * K + k0 + c);
            cp_async16(bbase + o, Wp + (size_t)row * K + k0 + c);
        }
        cp_commit();
    };

    issue_stage(0);

    for (int s = 0; s < S; s++) {
        cp_wait0();
        __syncthreads();
        if (s + 1 < S) issue_stage(s + 1);

        const int buf = s & 1;
        const uint32_t* Ab = smg + buf * 2 * GEMM_STAGE_UINTS + (wm * 64) * LDS_PAD;
        const uint32_t* Bb = smg + buf * 2 * GEMM_STAGE_UINTS + GEMM_STAGE_UINTS + (wn * 32) * LDS_PAD;
#pragma unroll
        for (int ks = 0; ks < 4; ks++) {
            uint32_t bf[4][2];
#pragma unroll
            for (int nt = 0; nt < 4; nt++) {
                const uint32_t* bp = Bb + (nt * 8 + g) * LDS_PAD + ks * 8 + tig;
                bf[nt][0] = bp[0];
                bf[nt][1] = bp[4];
            }
#pragma unroll
            for (int mt = 0; mt < 4; mt++) {
                uint32_t af[4];
                const uint32_t* ap = Ab + (mt * 16 + g) * LDS_PAD + ks * 8 + tig;
                af[0] = ap[0];
                af[1] = ap[8 * LDS_PAD];
                af[2] = ap[4];
                af[3] = ap[8 * LDS_PAD + 4];
#pragma unroll
                for (int nt = 0; nt < 4; nt++)
                    mma_tf32(acc[mt][nt], af, bf[nt]);
            }
        }
    }

    // epilogue
#pragma unroll
    for (int mt = 0; mt < 4; mt++) {
        int r0 = m0 + wm * 64 + mt * 16 + g;
#pragma unroll
        for (int half = 0; half < 2; half++) {
            int m = r0 + half * 8;
            float* Crow = C + (size_t)m * N + n0;
            const float* Rrow = (mode == 3) ? (res + (size_t)m * N + n0) : nullptr;
#pragma unroll
            for (int nt = 0; nt < 4; nt++) {
                int n = wn * 32 + nt * 8 + tig * 2;
                float2 o;
                o.x = acc[mt][nt][half * 2 + 0] + bias[n0 + n + 0];
                o.y = acc[mt][nt][half * 2 + 1] + bias[n0 + n + 1];
                if (mode == 2) {
                    o.x = __uint_as_float(f2tf32(fmaxf(o.x, 0.f)));
                    o.y = __uint_as_float(f2tf32(fmaxf(o.y, 0.f)));
                } else if (mode == 3) {
                    float2 rr = *(const float2*)(Rrow + n);
                    o.x += rr.x; o.y += rr.y;
                }
                *(float2*)(Crow + n) = o;
            }
        }
    }
}

// ---------------------------------------------------------------------------
// Transpose (T,B,E) -> (B,T,E), writes exact + rounded copies
// ---------------------------------------------------------------------------
__global__ __launch_bounds__(256) void transpose_in_kernel(const float* __restrict__ state)
{
    int m = blockIdx.x;
    int b = m / T_SEQ;
    int t = m % T_SEQ;
    float4 v = ((const float4*)(state + (size_t)t * B_SZ * EMB + (size_t)b * EMB))[threadIdx.x];
    ((float4*)(g_X0 + (size_t)m * EMB))[threadIdx.x] = v;
    float4 r;
    r.x = __uint_as_float(f2tf32(v.x));
    r.y = __uint_as_float(f2tf32(v.y));
    r.z = __uint_as_float(f2tf32(v.z));
    r.w = __uint_as_float(f2tf32(v.w));
    ((float4*)(g_X0r + (size_t)m * EMB))[threadIdx.x] = r;
}

// ---------------------------------------------------------------------------
// Flash attention with mma.sync tf32.
//   grid (T/128, B*H), 256 threads = 8 warps; warp w owns q-rows w*16..+15.
//   kv-block BN=64. S = Q K^T (HMMA), register softmax, P->SMEM(tf32), PV (HMMA).
// SMEM (uint): Qs[128][68], Ks[64][68], Vs[64][68], Ps[128][68]
// ---------------------------------------------------------------------------
#define AT_PAD 68
#define AT_SMEM_BYTES ((128 * AT_PAD + 64 * AT_PAD + 64 * AT_PAD + 128 * AT_PAD) * 4)

__global__ __launch_bounds__(256) void attn_mma_kernel(const uint8_t* __restrict__ mask)
{
    extern __shared__ uint32_t sma[];
    uint32_t* Qs = sma;
    uint32_t* Ks = Qs + 128 * AT_PAD;
    uint32_t* Vs = Ks + 64 * AT_PAD;
    uint32_t* Ps = Vs + 64 * AT_PAD;

    const int tq = blockIdx.x * 128;
    const int b = blockIdx.y >> 4;
    const int h = blockIdx.y & 15;
    const int tid = threadIdx.x;
    const int w = tid >> 5;
    const int lane = tid & 31;
    const int g = lane >> 2;
    const int tig = lane & 3;

    // fill Q tile (rounded to tf32)
    {
        const float* Qg = g_Q + (size_t)(b * T_SEQ + tq) * EMB + h * HD;
        for (int it = tid; it < 128 * 16; it += 256) {
            int r = it >> 4, c4 = (it & 15) * 4;
            float4 v = *(const float4*)(Qg + (size_t)r * EMB + c4);
            uint32_t* d = Qs + r * AT_PAD + c4;
            d[0] = f2tf32(v.x); d[1] = f2tf32(v.y); d[2] = f2tf32(v.z); d[3] = f2tf32(v.w);
        }
    }
    __syncthreads();

    // hoist Q fragments (8 k-steps over d=64)
    uint32_t qf[8][4];
    {
        const uint32_t* base = Qs + (w * 16 + g) * AT_PAD;
#pragma unroll
        for (int ks = 0; ks < 8; ks++) {
            qf[ks][0] = base[ks * 8 + tig];
            qf[ks][1] = base[8 * AT_PAD + ks * 8 + tig];
            qf[ks][2] = base[ks * 8 + tig + 4];
            qf[ks][3] = base[8 * AT_PAD + ks * 8 + tig + 4];
        }
    }

    float oacc[8][4];
#pragma unroll
    for (int nt = 0; nt < 8; nt++)
#pragma unroll
        for (int e = 0; e < 4; e++) oacc[nt][e] = 0.f;
    float mrow[2] = { -1e30f, -1e30f };
    float lrow[2] = { 0.f, 0.f };

    const uint8_t* mb = mask + (size_t)b * T_SEQ;

    for (int kt = 0; kt < T_SEQ; kt += 64) {
        __syncthreads();   // all warps done reading previous Ks/Vs
        {
            const float* Kg = g_K + (size_t)(b * T_SEQ + kt) * EMB + h * HD;
            const float* Vg = g_V + (size_t)(b * T_SEQ + kt) * EMB + h * HD;
            for (int it = tid; it < 64 * 16; it += 256) {
                int r = it >> 4, c4 = (it & 15) * 4;
                float4 kv = *(const float4*)(Kg + (size_t)r * EMB + c4);
                uint32_t* dk = Ks + r * AT_PAD + c4;
                dk[0] = f2tf32(kv.x); dk[1] = f2tf32(kv.y); dk[2] = f2tf32(kv.z); dk[3] = f2tf32(kv.w);
                float4 vv = *(const float4*)(Vg + (size_t)r * EMB + c4);
                uint32_t* dv = Vs + r * AT_PAD + c4;
                dv[0] = f2tf32(vv.x); dv[1] = f2tf32(vv.y); dv[2] = f2tf32(vv.z); dv[3] = f2tf32(vv.w);
            }
        }
        __syncthreads();

        // S = Q K^T : warp computes 16 x 64
        float sacc[8][4];
#pragma unroll
        for (int nt = 0; nt < 8; nt++)
#pragma unroll
            for (int e = 0; e < 4; e++) sacc[nt][e] = 0.f;

#pragma unroll
        for (int ks = 0; ks < 8; ks++) {
#pragma unroll
            for (int nt = 0; nt < 8; nt++) {
                uint32_t bf[2];
                const uint32_t* kp = Ks + (nt * 8 + g) * AT_PAD + ks * 8 + tig;
                bf[0] = kp[0];
                bf[1] = kp[4];
                mma_tf32(sacc[nt], qf[ks], bf);
            }
        }

        // scale + mask
#pragma unroll
        for (int nt = 0; nt < 8; nt++) {
            bool m0 = mb[kt + nt * 8 + 2 * tig] != 0;
            bool m1 = mb[kt + nt * 8 + 2 * tig + 1] != 0;
            sacc[nt][0] = m0 ? -1e30f : sacc[nt][0] * 0.125f;
            sacc[nt][1] = m1 ? -1e30f : sacc[nt][1] * 0.125f;
            sacc[nt][2] = m0 ? -1e30f : sacc[nt][2] * 0.125f;
            sacc[nt][3] = m1 ? -1e30f : sacc[nt][3] * 0.125f;
        }

        // online softmax per row-half (half 0: row g, vals 0/1; half 1: row g+8, vals 2/3)
#pragma unroll
        for (int half = 0; half < 2; half++) {
            float mx = -1e30f;
#pragma unroll
            for (int nt = 0; nt < 8; nt++) {
                mx = fmaxf(mx, sacc[nt][2 * half + 0]);
                mx = fmaxf(mx, sacc[nt][2 * half + 1]);
            }
            mx = fmaxf(mx, __shfl_xor_sync(0xffffffffu, mx, 1));
            mx = fmaxf(mx, __shfl_xor_sync(0xffffffffu, mx, 2));
            float mn = fmaxf(mrow[half], mx);
            float alpha = __expf(mrow[half] - mn);
            mrow[half] = mn;
            float rs = 0.f;
            uint32_t* prow = Ps + (w * 16 + g + half * 8) * AT_PAD;
#pragma unroll
            for (int nt = 0; nt < 8; nt++) {
                float p0 = __expf(sacc[nt][2 * half + 0] - mn);
                float p1 = __expf(sacc[nt][2 * half + 1] - mn);
                rs += p0 + p1;
                prow[nt * 8 + 2 * tig + 0] = f2tf32(p0);
                prow[nt * 8 + 2 * tig + 1] = f2tf32(p1);
            }
            rs += __shfl_xor_sync(0xffffffffu, rs, 1);
            rs += __shfl_xor_sync(0xffffffffu, rs, 2);
            lrow[half] = lrow[half] * alpha + rs;
#pragma unroll
            for (int nt = 0; nt < 8; nt++) {
                oacc[nt][2 * half + 0] *= alpha;
                oacc[nt][2 * half + 1] *= alpha;
            }
        }
        __syncwarp();   // P visible within warp

        // O += P V : warp 16 x 64, k-depth 64 (kv)
#pragma unroll
        for (int ks = 0; ks < 8; ks++) {
            uint32_t af[4];
            const uint32_t* pp = Ps + (w * 16 + g) * AT_PAD + ks * 8 + tig;
            af[0] = pp[0];
            af[1] = pp[8 * AT_PAD];
            af[2] = pp[4];
            af[3] = pp[8 * AT_PAD + 4];
#pragma unroll
            for (int nt = 0; nt < 8; nt++) {
                uint32_t bf[2];
                const uint32_t* vp = Vs + (ks * 8 + tig) * AT_PAD + nt * 8 + g;
                bf[0] = vp[0];
                bf[1] = vp[4 * AT_PAD];
                mma_tf32(oacc[nt], af, bf);
            }
        }
        __syncwarp();   // P reads done before next block's stores
    }

    // write output (rounded to tf32 — consumed only by the out-proj GEMM)
#pragma unroll
    for (int half = 0; half < 2; half++) {
        float inv = 1.f / lrow[half];
        int r = tq + w * 16 + g + half * 8;
        float* dst = g_ATTN + (size_t)(b * T_SEQ + r) * EMB + h * HD;
#pragma unroll
        for (int nt = 0; nt < 8; nt++) {
            float2 o;
            o.x = __uint_as_float(f2tf32(oacc[nt][2 * half + 0] * inv));
            o.y = __uint_as_float(f2tf32(oacc[nt][2 * half + 1] * inv));
            *(float2*)(dst + nt * 8 + 2 * tig) = o;
        }
    }
}

// ---------------------------------------------------------------------------
// LayerNorm (E=1024). Optionally writes a rounded copy.
// ---------------------------------------------------------------------------
__global__ __launch_bounds__(256) void ln_kernel(
    const float* __restrict__ X, const float* __restrict__ gw,
    const float* __restrict__ bw, float* __restrict__ out,
    float* __restrict__ out_r, int transposed)
{
    int m = blockIdx.x;
    float4 v = ((const float4*)(X + (size_t)m * EMB))[threadIdx.x];
    float s = v.x + v.y + v.z + v.w;
    float sq = v.x * v.x + v.y * v.y + v.z * v.z + v.w * v.w;

    __shared__ float rs[256], rq[256];
    rs[threadIdx.x] = s; rq[threadIdx.x] = sq;
    __syncthreads();
    for (int st = 128; st > 0; st >>= 1) {
        if (threadIdx.x < st) {
            rs[threadIdx.x] += rs[threadIdx.x + st];
            rq[threadIdx.x] += rq[threadIdx.x + st];
        }
        __syncthreads();
    }
    float mu  = rs[0] * (1.f / EMB);
    float var = rq[0] * (1.f / EMB) - mu * mu;
    float inv = rsqrtf(var + 1e-5f);

    float4 g4 = ((const float4*)gw)[threadIdx.x];
    float4 b4 = ((const float4*)bw)[threadIdx.x];
    float4 o;
    o.x = (v.x - mu) * inv * g4.x + b4.x;
    o.y = (v.y - mu) * inv * g4.y + b4.y;
    o.z = (v.z - mu) * inv * g4.z + b4.z;
    o.w = (v.w - mu) * inv * g4.w + b4.w;

    size_t obase;
    if (transposed) {
        int b = m / T_SEQ, t = m % T_SEQ;
        obase = (size_t)t * B_SZ * EMB + (size_t)b * EMB;
    } else {
        obase = (size_t)m * EMB;
    }
    ((float4*)(out + obase))[threadIdx.x] = o;
    if (out_r) {
        float4 r;
        r.x = __uint_as_float(f2tf32(o.x));
        r.y = __uint_as_float(f2tf32(o.y));
        r.z = __uint_as_float(f2tf32(o.z));
        r.w = __uint_as_float(f2tf32(o.w));
        ((float4*)(out_r + (size_t)m * EMB))[threadIdx.x] = r;
    }
}

// ---------------------------------------------------------------------------
extern "C" void kernel_launch(void* const* d_in, const int* in_sizes, int n_in,
                              void* d_out, int out_size)
{
    const float*   state = (const float*)d_in[0];
    const uint8_t* mask  = (const uint8_t*)d_in[1];
    const float* q_w  = (const float*)d_in[2];
    const float* q_b  = (const float*)d_in[3];
    const float* k_w  = (const float*)d_in[4];
    const float* k_b  = (const float*)d_in[5];
    const float* v_w  = (const float*)d_in[6];
    const float* v_b  = (const float*)d_in[7];
    const float* out_w = (const float*)d_in[8];
    const float* out_b = (const float*)d_in[9];
    const float* ln1_g = (const float*)d_in[10];
    const float* ln1_b = (const float*)d_in[11];
    const float* fc1_w = (const float*)d_in[12];
    const float* fc1_b = (const float*)d_in[13];
    const float* fc2_w = (const float*)d_in[14];
    const float* fc2_b = (const float*)d_in[15];
    const float* ln2_g = (const float*)d_in[16];
    const float* ln2_b = (const float*)d_in[17];
    float* out = (float*)d_out;

    float *pX0, *pX0r, *pQ, *pK, *pV, *pATTN, *pY, *pX1, *pX1r, *pH;
    float *pWQ, *pWK, *pWV, *pWO, *pW1, *pW2;
    cudaGetSymbolAddress((void**)&pX0,   g_X0);
    cudaGetSymbolAddress((void**)&pX0r,  g_X0r);
    cudaGetSymbolAddress((void**)&pQ,    g_Q);
    cudaGetSymbolAddress((void**)&pK,    g_K);
    cudaGetSymbolAddress((void**)&pV,    g_V);
    cudaGetSymbolAddress((void**)&pATTN, g_ATTN);
    cudaGetSymbolAddress((void**)&pY,    g_Y);
    cudaGetSymbolAddress((void**)&pX1,   g_X1);
    cudaGetSymbolAddress((void**)&pX1r,  g_X1r);
    cudaGetSymbolAddress((void**)&pH,    g_H);
    cudaGetSymbolAddress((void**)&pWQ,   g_WQr);
    cudaGetSymbolAddress((void**)&pWK,   g_WKr);
    cudaGetSymbolAddress((void**)&pWV,   g_WVr);
    cudaGetSymbolAddress((void**)&pWO,   g_WOr);
    cudaGetSymbolAddress((void**)&pW1,   g_W1r);
    cudaGetSymbolAddress((void**)&pW2,   g_W2r);

    cudaFuncSetAttribute(attn_mma_kernel, cudaFuncAttributeMaxDynamicSharedMemorySize,
                         AT_SMEM_BYTES);
    cudaFuncSetAttribute(gemm_tc_kernel, cudaFuncAttributeMaxDynamicSharedMemorySize,
                         GEMM_SMEM_BYTES);

    // 0. round weights to tf32 (+ transpose input, writing exact + rounded)
    const int NW1 = EMB * EMB;
    round_tf32_kernel<<<NW1 / 1024, 256>>>(q_w,  pWQ, NW1);
    round_tf32_kernel<<<NW1 / 1024, 256>>>(k_w,  pWK, NW1);
    round_tf32_kernel<<<NW1 / 1024, 256>>>(v_w,  pWV, NW1);
    round_tf32_kernel<<<NW1 / 1024, 256>>>(out_w, pWO, NW1);
    round_tf32_kernel<<<FFN_DIM * EMB / 1024, 256>>>(fc1_w, pW1, FFN_DIM * EMB);
    round_tf32_kernel<<<EMB * FFN_DIM / 1024, 256>>>(fc2_w, pW2, EMB * FFN_DIM);
    transpose_in_kernel<<<MTOK, 256>>>(state);

    // 1. QKV projections
    dim3 gProj(EMB / 128, MTOK / 128);
    gemm_tc_kernel<<<gProj, 256, GEMM_SMEM_BYTES>>>(pX0r, pWQ, q_b, nullptr, pQ, MTOK, EMB, EMB, 0);
    gemm_tc_kernel<<<gProj, 256, GEMM_SMEM_BYTES>>>(pX0r, pWK, k_b, nullptr, pK, MTOK, EMB, EMB, 0);
    gemm_tc_kernel<<<gProj, 256, GEMM_SMEM_BYTES>>>(pX0r, pWV, v_b, nullptr, pV, MTOK, EMB, EMB, 0);

    // 2. attention (tensor-core flash attention)
    dim3 gAttn(T_SEQ / 128, B_SZ * NHEADS);
    attn_mma_kernel<<<gAttn, 256, AT_SMEM_BYTES>>>(mask);

    // 3. out projection + residual(X0 exact)
    gemm_tc_kernel<<<gProj, 256, GEMM_SMEM_BYTES>>>(pATTN, pWO, out_b, pX0, pY, MTOK, EMB, EMB, 3);

    // 4. LN1 -> X1 exact + X1r rounded
    ln_kernel<<<MTOK, 256>>>(pY, ln1_g, ln1_b, pX1, pX1r, 0);

    // 5. fc1 + relu (+round: H only feeds fc2)
    dim3 gFc1(FFN_DIM / 128, MTOK / 128);
    gemm_tc_kernel<<<gFc1, 256, GEMM_SMEM_BYTES>>>(pX1r, pW1, fc1_b, nullptr, pH, MTOK, FFN_DIM, EMB, 2);

    // 6. fc2 + residual(X1 exact)
    gemm_tc_kernel<<<gProj, 256, GEMM_SMEM_BYTES>>>(pH, pW2, fc2_b, pX1, pY, MTOK, EMB, FFN_DIM, 3);

    // 7. LN2 -> output (T,B,E)
    ln_kernel<<<MTOK, 256>>>(pY, ln2_g, ln2_b, out, nullptr, 1);
}

// round 6
// speedup vs baseline: 3.4838x; 1.0109x over previous
#include <cuda_runtime.h>
#include <math.h>
#include <stdint.h>

// Problem constants
#define T_SEQ 2048
#define B_SZ  4
#define EMB   1024
#define NHEADS 16
#define HD    64
#define FFN_DIM 4096
#define MTOK  (T_SEQ * B_SZ)   // 8192 tokens

// ---------------- scratch (device globals; no cudaMalloc allowed) ----------
__device__ float g_X0 [MTOK * EMB];      // exact token-major input
__device__ float g_X0r[MTOK * EMB];      // tf32-rounded copy
__device__ float g_Q  [MTOK * EMB];
__device__ float g_K  [MTOK * EMB];
__device__ float g_V  [MTOK * EMB];
__device__ float g_ATTN[MTOK * EMB];     // rounded attention output
__device__ float g_Y  [MTOK * EMB];
__device__ float g_X1 [MTOK * EMB];      // exact LN1 out
__device__ float g_X1r[MTOK * EMB];      // rounded LN1 out
__device__ float g_H  [MTOK * FFN_DIM];  // rounded relu(fc1)
// rounded weights
__device__ float g_WQr[EMB * EMB];
__device__ float g_WKr[EMB * EMB];
__device__ float g_WVr[EMB * EMB];
__device__ float g_WOr[EMB * EMB];
__device__ float g_W1r[FFN_DIM * EMB];
__device__ float g_W2r[EMB * FFN_DIM];

// ---------------------------------------------------------------------------
__device__ __forceinline__ uint32_t smem_u32(const void* p) {
    uint32_t a;
    asm("{ .reg .u64 t; cvta.to.shared.u64 t, %1; cvt.u32.u64 %0, t; }" : "=r"(a) : "l"(p));
    return a;
}
__device__ __forceinline__ uint32_t f2tf32(float f) {
    uint32_t r;
    asm("cvt.rna.tf32.f32 %0, %1;" : "=r"(r) : "f"(f));
    return r;
}
__device__ __forceinline__ void mma_tf32(float* d, const uint32_t* a, const uint32_t* b) {
    asm volatile(
        "mma.sync.aligned.m16n8k8.row.col.f32.tf32.tf32.f32 "
        "{%0,%1,%2,%3}, {%4,%5,%6,%7}, {%8,%9}, {%0,%1,%2,%3};"
        : "+f"(d[0]), "+f"(d[1]), "+f"(d[2]), "+f"(d[3])
        : "r"(a[0]), "r"(a[1]), "r"(a[2]), "r"(a[3]), "r"(b[0]), "r"(b[1]));
}
__device__ __forceinline__ void cp_async16(uint32_t dst, const void* src) {
    asm volatile("cp.async.cg.shared.global [%0], [%1], 16;" :: "r"(dst), "l"(src));
}
__device__ __forceinline__ void cp_commit() { asm volatile("cp.async.commit_group;"); }
__device__ __forceinline__ void cp_wait1()  { asm volatile("cp.async.wait_group 1;"); }

// ---------------------------------------------------------------------------
// Round fp32 -> tf32-valued fp32 (elementwise, float4)
// ---------------------------------------------------------------------------
__global__ __launch_bounds__(256) void round_tf32_kernel(
    const float* __restrict__ src, float* __restrict__ dst, int n)
{
    int i = (blockIdx.x * 256 + threadIdx.x) * 4;
    if (i < n) {
        float4 v = *(const float4*)(src + i);
        float4 o;
        o.x = __uint_as_float(f2tf32(v.x));
        o.y = __uint_as_float(f2tf32(v.y));
        o.z = __uint_as_float(f2tf32(v.z));
        o.w = __uint_as_float(f2tf32(v.w));
        *(float4*)(dst + i) = o;
    }
}

// ---------------------------------------------------------------------------
// Tensor-core GEMM via mma.sync tf32, 3-stage cp.async pipeline.
//   Inputs A and W must be tf32-valued fp32 already.
//   C[m,n] = sum_k A[m,k]*W[n,k] + bias[n]
//   mode 0: plain   mode 2: relu + round-to-tf32   mode 3: + res
//   CTA 128x256, BK=32, 8 warps (2m x 4n), warp tile 64x64.
// SMEM per stage: A[128][36] + B[256][36] floats
// ---------------------------------------------------------------------------
#define LDS_PAD 36
#define STG_A_UINTS (128 * LDS_PAD)
#define STG_B_UINTS (256 * LDS_PAD)
#define STG_UINTS   (STG_A_UINTS + STG_B_UINTS)        // 13824
#define GEMM_SMEM_BYTES (3 * STG_UINTS * 4)            // 165888

__global__ __launch_bounds__(256, 1) void gemm_tc_kernel(
    const float* __restrict__ A, const float* __restrict__ W,
    const float* __restrict__ bias, const float* __restrict__ res,
    float* __restrict__ C, int M, int N, int K, int mode)
{
    extern __shared__ uint32_t smg[];
    const uint32_t sbase = smem_u32(smg);

    const int tid = threadIdx.x;
    const int wid = tid >> 5;
    const int lane = tid & 31;
    const int g   = lane >> 2;
    const int tig = lane & 3;
    const int wm = wid >> 2;     // 0..1
    const int wn = wid & 3;      // 0..3
    const int m0 = blockIdx.y * 128;
    const int n0 = blockIdx.x * 256;

    const float* Ap = A + (size_t)m0 * K;
    const float* Wp = W + (size_t)n0 * K;

    float acc[4][8][4];
#pragma unroll
    for (int mt = 0; mt < 4; mt++)
#pragma unroll
        for (int nt = 0; nt < 8; nt++)
#pragma unroll
            for (int e = 0; e < 4; e++) acc[mt][nt][e] = 0.f;

    const int S = K >> 5;

    auto issue_stage = [&](int s) {
        const int buf = s % 3;
        const int k0 = s << 5;
        const uint32_t abase = sbase + (uint32_t)(buf * STG_UINTS) * 4;
        const uint32_t bbase = abase + STG_A_UINTS * 4;
        // A tile: 128 rows x 32 floats
#pragma unroll
        for (int i = 0; i < 4; i++) {
            int idx = tid + 256 * i;
            int row = idx >> 3, c = (idx & 7) << 2;
            cp_async16(abase + (uint32_t)(row * LDS_PAD + c) * 4,
                       Ap + (size_t)row * K + k0 + c);
        }
        // B tile: 256 rows x 32 floats
#pragma unroll
        for (int i = 0; i < 8; i++) {
            int idx = tid + 256 * i;
            int row = idx >> 3, c = (idx & 7) << 2;
            cp_async16(bbase + (uint32_t)(row * LDS_PAD + c) * 4,
                       Wp + (size_t)row * K + k0 + c);
        }
        cp_commit();
    };

    issue_stage(0);
    issue_stage(1);

    for (int s = 0; s < S; s++) {
        cp_wait1();          // stage s arrived (<=1 group pending)
        __syncthreads();     // all warps past compute(s-1): buffer (s+2)%3 free
        if (s + 2 < S) issue_stage(s + 2);

        const int buf = s % 3;
        const uint32_t* Ab = smg + buf * STG_UINTS + (wm * 64) * LDS_PAD;
        const uint32_t* Bb = smg + buf * STG_UINTS + STG_A_UINTS + (wn * 64) * LDS_PAD;
#pragma unroll
        for (int ks = 0; ks < 4; ks++) {
            uint32_t bf[8][2];
#pragma unroll
            for (int nt = 0; nt < 8; nt++) {
                const uint32_t* bp = Bb + (nt * 8 + g) * LDS_PAD + ks * 8 + tig;
                bf[nt][0] = bp[0];
                bf[nt][1] = bp[4];
            }
#pragma unroll
            for (int mt = 0; mt < 4; mt++) {
                uint32_t af[4];
                const uint32_t* ap = Ab + (mt * 16 + g) * LDS_PAD + ks * 8 + tig;
                af[0] = ap[0];
                af[1] = ap[8 * LDS_PAD];
                af[2] = ap[4];
                af[3] = ap[8 * LDS_PAD + 4];
#pragma unroll
                for (int nt = 0; nt < 8; nt++)
                    mma_tf32(acc[mt][nt], af, bf[nt]);
            }
        }
    }

    // epilogue
#pragma unroll
    for (int mt = 0; mt < 4; mt++) {
        int r0 = m0 + wm * 64 + mt * 16 + g;
#pragma unroll
        for (int half = 0; half < 2; half++) {
            int m = r0 + half * 8;
            float* Crow = C + (size_t)m * N + n0;
            const float* Rrow = (mode == 3) ? (res + (size_t)m * N + n0) : nullptr;
#pragma unroll
            for (int nt = 0; nt < 8; nt++) {
                int n = wn * 64 + nt * 8 + tig * 2;
                float2 o;
                o.x = acc[mt][nt][half * 2 + 0] + bias[n0 + n + 0];
                o.y = acc[mt][nt][half * 2 + 1] + bias[n0 + n + 1];
                if (mode == 2) {
                    o.x = __uint_as_float(f2tf32(fmaxf(o.x, 0.f)));
                    o.y = __uint_as_float(f2tf32(fmaxf(o.y, 0.f)));
                } else if (mode == 3) {
                    float2 rr = *(const float2*)(Rrow + n);
                    o.x += rr.x; o.y += rr.y;
                }
                *(float2*)(Crow + n) = o;
            }
        }
    }
}

// ---------------------------------------------------------------------------
// Transpose (T,B,E) -> (B,T,E), writes exact + rounded copies
// ---------------------------------------------------------------------------
__global__ __launch_bounds__(256) void transpose_in_kernel(const float* __restrict__ state)
{
    int m = blockIdx.x;
    int b = m / T_SEQ;
    int t = m % T_SEQ;
    float4 v = ((const float4*)(state + (size_t)t * B_SZ * EMB + (size_t)b * EMB))[threadIdx.x];
    ((float4*)(g_X0 + (size_t)m * EMB))[threadIdx.x] = v;
    float4 r;
    r.x = __uint_as_float(f2tf32(v.x));
    r.y = __uint_as_float(f2tf32(v.y));
    r.z = __uint_as_float(f2tf32(v.z));
    r.w = __uint_as_float(f2tf32(v.w));
    ((float4*)(g_X0r + (size_t)m * EMB))[threadIdx.x] = r;
}

// ---------------------------------------------------------------------------
// Flash attention with mma.sync tf32 (unchanged from R4).
// ---------------------------------------------------------------------------
#define AT_PAD 68
#define AT_SMEM_BYTES ((128 * AT_PAD + 64 * AT_PAD + 64 * AT_PAD + 128 * AT_PAD) * 4)

__global__ __launch_bounds__(256) void attn_mma_kernel(const uint8_t* __restrict__ mask)
{
    extern __shared__ uint32_t sma[];
    uint32_t* Qs = sma;
    uint32_t* Ks = Qs + 128 * AT_PAD;
    uint32_t* Vs = Ks + 64 * AT_PAD;
    uint32_t* Ps = Vs + 64 * AT_PAD;

    const int tq = blockIdx.x * 128;
    const int b = blockIdx.y >> 4;
    const int h = blockIdx.y & 15;
    const int tid = threadIdx.x;
    const int w = tid >> 5;
    const int lane = tid & 31;
    const int g = lane >> 2;
    const int tig = lane & 3;

    {
        const float* Qg = g_Q + (size_t)(b * T_SEQ + tq) * EMB + h * HD;
        for (int it = tid; it < 128 * 16; it += 256) {
            int r = it >> 4, c4 = (it & 15) * 4;
            float4 v = *(const float4*)(Qg + (size_t)r * EMB + c4);
            uint32_t* d = Qs + r * AT_PAD + c4;
            d[0] = f2tf32(v.x); d[1] = f2tf32(v.y); d[2] = f2tf32(v.z); d[3] = f2tf32(v.w);
        }
    }
    __syncthreads();

    uint32_t qf[8][4];
    {
        const uint32_t* base = Qs + (w * 16 + g) * AT_PAD;
#pragma unroll
        for (int ks = 0; ks < 8; ks++) {
            qf[ks][0] = base[ks * 8 + tig];
            qf[ks][1] = base[8 * AT_PAD + ks * 8 + tig];
            qf[ks][2] = base[ks * 8 + tig + 4];
            qf[ks][3] = base[8 * AT_PAD + ks * 8 + tig + 4];
        }
    }

    float oacc[8][4];
#pragma unroll
    for (int nt = 0; nt < 8; nt++)
#pragma unroll
        for (int e = 0; e < 4; e++) oacc[nt][e] = 0.f;
    float mrow[2] = { -1e30f, -1e30f };
    float lrow[2] = { 0.f, 0.f };

    const uint8_t* mb = mask + (size_t)b * T_SEQ;

    for (int kt = 0; kt < T_SEQ; kt += 64) {
        __syncthreads();
        {
            const float* Kg = g_K + (size_t)(b * T_SEQ + kt) * EMB + h * HD;
            const float* Vg = g_V + (size_t)(b * T_SEQ + kt) * EMB + h * HD;
            for (int it = tid; it < 64 * 16; it += 256) {
                int r = it >> 4, c4 = (it & 15) * 4;
                float4 kv = *(const float4*)(Kg + (size_t)r * EMB + c4);
                uint32_t* dk = Ks + r * AT_PAD + c4;
                dk[0] = f2tf32(kv.x); dk[1] = f2tf32(kv.y); dk[2] = f2tf32(kv.z); dk[3] = f2tf32(kv.w);
                float4 vv = *(const float4*)(Vg + (size_t)r * EMB + c4);
                uint32_t* dv = Vs + r * AT_PAD + c4;
                dv[0] = f2tf32(vv.x); dv[1] = f2tf32(vv.y); dv[2] = f2tf32(vv.z); dv[3] = f2tf32(vv.w);
            }
        }
        __syncthreads();

        float sacc[8][4];
#pragma unroll
        for (int nt = 0; nt < 8; nt++)
#pragma unroll
            for (int e = 0; e < 4; e++) sacc[nt][e] = 0.f;

#pragma unroll
        for (int ks = 0; ks < 8; ks++) {
#pragma unroll
            for (int nt = 0; nt < 8; nt++) {
                uint32_t bf[2];
                const uint32_t* kp = Ks + (nt * 8 + g) * AT_PAD + ks * 8 + tig;
                bf[0] = kp[0];
                bf[1] = kp[4];
                mma_tf32(sacc[nt], qf[ks], bf);
            }
        }

#pragma unroll
        for (int nt = 0; nt < 8; nt++) {
            bool m0 = mb[kt + nt * 8 + 2 * tig] != 0;
            bool m1 = mb[kt + nt * 8 + 2 * tig + 1] != 0;
            sacc[nt][0] = m0 ? -1e30f : sacc[nt][0] * 0.125f;
            sacc[nt][1] = m1 ? -1e30f : sacc[nt][1] * 0.125f;
            sacc[nt][2] = m0 ? -1e30f : sacc[nt][2] * 0.125f;
            sacc[nt][3] = m1 ? -1e30f : sacc[nt][3] * 0.125f;
        }

#pragma unroll
        for (int half = 0; half < 2; half++) {
            float mx = -1e30f;
#pragma unroll
            for (int nt = 0; nt < 8; nt++) {
                mx = fmaxf(mx, sacc[nt][2 * half + 0]);
                mx = fmaxf(mx, sacc[nt][2 * half + 1]);
            }
            mx = fmaxf(mx, __shfl_xor_sync(0xffffffffu, mx, 1));
            mx = fmaxf(mx, __shfl_xor_sync(0xffffffffu, mx, 2));
            float mn = fmaxf(mrow[half], mx);
            float alpha = __expf(mrow[half] - mn);
            mrow[half] = mn;
            float rs = 0.f;
            uint32_t* prow = Ps + (w * 16 + g + half * 8) * AT_PAD;
#pragma unroll
            for (int nt = 0; nt < 8; nt++) {
                float p0 = __expf(sacc[nt][2 * half + 0] - mn);
                float p1 = __expf(sacc[nt][2 * half + 1] - mn);
                rs += p0 + p1;
                prow[nt * 8 + 2 * tig + 0] = f2tf32(p0);
                prow[nt * 8 + 2 * tig + 1] = f2tf32(p1);
            }
            rs += __shfl_xor_sync(0xffffffffu, rs, 1);
            rs += __shfl_xor_sync(0xffffffffu, rs, 2);
            lrow[half] = lrow[half] * alpha + rs;
#pragma unroll
            for (int nt = 0; nt < 8; nt++) {
                oacc[nt][2 * half + 0] *= alpha;
                oacc[nt][2 * half + 1] *= alpha;
            }
        }
        __syncwarp();

#pragma unroll
        for (int ks = 0; ks < 8; ks++) {
            uint32_t af[4];
            const uint32_t* pp = Ps + (w * 16 + g) * AT_PAD + ks * 8 + tig;
            af[0] = pp[0];
            af[1] = pp[8 * AT_PAD];
            af[2] = pp[4];
            af[3] = pp[8 * AT_PAD + 4];
#pragma unroll
            for (int nt = 0; nt < 8; nt++) {
                uint32_t bf[2];
                const uint32_t* vp = Vs + (ks * 8 + tig) * AT_PAD + nt * 8 + g;
                bf[0] = vp[0];
                bf[1] = vp[4 * AT_PAD];
                mma_tf32(oacc[nt], af, bf);
            }
        }
        __syncwarp();
    }

#pragma unroll
    for (int half = 0; half < 2; half++) {
        float inv = 1.f / lrow[half];
        int r = tq + w * 16 + g + half * 8;
        float* dst = g_ATTN + (size_t)(b * T_SEQ + r) * EMB + h * HD;
#pragma unroll
        for (int nt = 0; nt < 8; nt++) {
            float2 o;
            o.x = __uint_as_float(f2tf32(oacc[nt][2 * half + 0] * inv));
            o.y = __uint_as_float(f2tf32(oacc[nt][2 * half + 1] * inv));
            *(float2*)(dst + nt * 8 + 2 * tig) = o;
        }
    }
}

// ---------------------------------------------------------------------------
// LayerNorm (E=1024). Optionally writes a rounded copy.
// ---------------------------------------------------------------------------
__global__ __launch_bounds__(256) void ln_kernel(
    const float* __restrict__ X, const float* __restrict__ gw,
    const float* __restrict__ bw, float* __restrict__ out,
    float* __restrict__ out_r, int transposed)
{
    int m = blockIdx.x;
    float4 v = ((const float4*)(X + (size_t)m * EMB))[threadIdx.x];
    float s = v.x + v.y + v.z + v.w;
    float sq = v.x * v.x + v.y * v.y + v.z * v.z + v.w * v.w;

    __shared__ float rs[256], rq[256];
    rs[threadIdx.x] = s; rq[threadIdx.x] = sq;
    __syncthreads();
    for (int st = 128; st > 0; st >>= 1) {
        if (threadIdx.x < st) {
            rs[threadIdx.x] += rs[threadIdx.x + st];
            rq[threadIdx.x] += rq[threadIdx.x + st];
        }
        __syncthreads();
    }
    float mu  = rs[0] * (1.f / EMB);
    float var = rq[0] * (1.f / EMB) - mu * mu;
    float inv = rsqrtf(var + 1e-5f);

    float4 g4 = ((const float4*)gw)[threadIdx.x];
    float4 b4 = ((const float4*)bw)[threadIdx.x];
    float4 o;
    o.x = (v.x - mu) * inv * g4.x + b4.x;
    o.y = (v.y - mu) * inv * g4.y + b4.y;
    o.z = (v.z - mu) * inv * g4.z + b4.z;
    o.w = (v.w - mu) * inv * g4.w + b4.w;

    size_t obase;
    if (transposed) {
        int b = m / T_SEQ, t = m % T_SEQ;
        obase = (size_t)t * B_SZ * EMB + (size_t)b * EMB;
    } else {
        obase = (size_t)m * EMB;
    }
    ((float4*)(out + obase))[threadIdx.x] = o;
    if (out_r) {
        float4 r;
        r.x = __uint_as_float(f2tf32(o.x));
        r.y = __uint_as_float(f2tf32(o.y));
        r.z = __uint_as_float(f2tf32(o.z));
        r.w = __uint_as_float(f2tf32(o.w));
        ((float4*)(out_r + (size_t)m * EMB))[threadIdx.x] = r;
    }
}

// ---------------------------------------------------------------------------
extern "C" void kernel_launch(void* const* d_in, const int* in_sizes, int n_in,
                              void* d_out, int out_size)
{
    const float*   state = (const float*)d_in[0];
    const uint8_t* mask  = (const uint8_t*)d_in[1];
    const float* q_w  = (const float*)d_in[2];
    const float* q_b  = (const float*)d_in[3];
    const float* k_w  = (const float*)d_in[4];
    const float* k_b  = (const float*)d_in[5];
    const float* v_w  = (const float*)d_in[6];
    const float* v_b  = (const float*)d_in[7];
    const float* out_w = (const float*)d_in[8];
    const float* out_b = (const float*)d_in[9];
    const float* ln1_g = (const float*)d_in[10];
    const float* ln1_b = (const float*)d_in[11];
    const float* fc1_w = (const float*)d_in[12];
    const float* fc1_b = (const float*)d_in[13];
    const float* fc2_w = (const float*)d_in[14];
    const float* fc2_b = (const float*)d_in[15];
    const float* ln2_g = (const float*)d_in[16];
    const float* ln2_b = (const float*)d_in[17];
    float* out = (float*)d_out;

    float *pX0, *pX0r, *pQ, *pK, *pV, *pATTN, *pY, *pX1, *pX1r, *pH;
    float *pWQ, *pWK, *pWV, *pWO, *pW1, *pW2;
    cudaGetSymbolAddress((void**)&pX0,   g_X0);
    cudaGetSymbolAddress((void**)&pX0r,  g_X0r);
    cudaGetSymbolAddress((void**)&pQ,    g_Q);
    cudaGetSymbolAddress((void**)&pK,    g_K);
    cudaGetSymbolAddress((void**)&pV,    g_V);
    cudaGetSymbolAddress((void**)&pATTN, g_ATTN);
    cudaGetSymbolAddress((void**)&pY,    g_Y);
    cudaGetSymbolAddress((void**)&pX1,   g_X1);
    cudaGetSymbolAddress((void**)&pX1r,  g_X1r);
    cudaGetSymbolAddress((void**)&pH,    g_H);
    cudaGetSymbolAddress((void**)&pWQ,   g_WQr);
    cudaGetSymbolAddress((void**)&pWK,   g_WKr);
    cudaGetSymbolAddress((void**)&pWV,   g_WVr);
    cudaGetSymbolAddress((void**)&pWO,   g_WOr);
    cudaGetSymbolAddress((void**)&pW1,   g_W1r);
    cudaGetSymbolAddress((void**)&pW2,   g_W2r);

    cudaFuncSetAttribute(attn_mma_kernel, cudaFuncAttributeMaxDynamicSharedMemorySize,
                         AT_SMEM_BYTES);
    cudaFuncSetAttribute(gemm_tc_kernel, cudaFuncAttributeMaxDynamicSharedMemorySize,
                         GEMM_SMEM_BYTES);

    // 0. round weights to tf32 (+ transpose input, exact + rounded)
    const int NW1 = EMB * EMB;
    round_tf32_kernel<<<NW1 / 1024, 256>>>(q_w,  pWQ, NW1);
    round_tf32_kernel<<<NW1 / 1024, 256>>>(k_w,  pWK, NW1);
    round_tf32_kernel<<<NW1 / 1024, 256>>>(v_w,  pWV, NW1);
    round_tf32_kernel<<<NW1 / 1024, 256>>>(out_w, pWO, NW1);
    round_tf32_kernel<<<FFN_DIM * EMB / 1024, 256>>>(fc1_w, pW1, FFN_DIM * EMB);
    round_tf32_kernel<<<EMB * FFN_DIM / 1024, 256>>>(fc2_w, pW2, EMB * FFN_DIM);
    transpose_in_kernel<<<MTOK, 256>>>(state);

    // 1. QKV projections
    dim3 gProj(EMB / 256, MTOK / 128);
    gemm_tc_kernel<<<gProj, 256, GEMM_SMEM_BYTES>>>(pX0r, pWQ, q_b, nullptr, pQ, MTOK, EMB, EMB, 0);
    gemm_tc_kernel<<<gProj, 256, GEMM_SMEM_BYTES>>>(pX0r, pWK, k_b, nullptr, pK, MTOK, EMB, EMB, 0);
    gemm_tc_kernel<<<gProj, 256, GEMM_SMEM_BYTES>>>(pX0r, pWV, v_b, nullptr, pV, MTOK, EMB, EMB, 0);

    // 2. attention
    dim3 gAttn(T_SEQ / 128, B_SZ * NHEADS);
    attn_mma_kernel<<<gAttn, 256, AT_SMEM_BYTES>>>(mask);

    // 3. out projection + residual(X0 exact)
    gemm_tc_kernel<<<gProj, 256, GEMM_SMEM_BYTES>>>(pATTN, pWO, out_b, pX0, pY, MTOK, EMB, EMB, 3);

    // 4. LN1 -> X1 exact + X1r rounded
    ln_kernel<<<MTOK, 256>>>(pY, ln1_g, ln1_b, pX1, pX1r, 0);

    // 5. fc1 + relu (+round)
    dim3 gFc1(FFN_DIM / 256, MTOK / 128);
    gemm_tc_kernel<<<gFc1, 256, GEMM_SMEM_BYTES>>>(pX1r, pW1, fc1_b, nullptr, pH, MTOK, FFN_DIM, EMB, 2);

    // 6. fc2 + residual(X1 exact)
    gemm_tc_kernel<<<gProj, 256, GEMM_SMEM_BYTES>>>(pH, pW2, fc2_b, pX1, pY, MTOK, EMB, FFN_DIM, 3);

    // 7. LN2 -> output (T,B,E)
    ln_kernel<<<MTOK, 256>>>(pY, ln2_g, ln2_b, out, nullptr, 1);
}

// round 7
// speedup vs baseline: 5.1772x; 1.4861x over previous
#include <cuda_runtime.h>
#include <cuda_fp16.h>
#include <math.h>
#include <stdint.h>

// Problem constants
#define T_SEQ 2048
#define B_SZ  4
#define EMB   1024
#define NHEADS 16
#define HD    64
#define FFN_DIM 4096
#define MTOK  (T_SEQ * B_SZ)   // 8192 tokens

// ---------------- scratch (device globals; no cudaMalloc allowed) ----------
__device__ float  g_X0 [MTOK * EMB];      // exact token-major input (residual)
__device__ float  g_Y  [MTOK * EMB];      // pre-LN sum
__device__ float  g_X1 [MTOK * EMB];      // exact LN1 out (residual)
__device__ __half g_X0h[MTOK * EMB];      // fp16 copies (GEMM operands)
__device__ __half g_Qh [MTOK * EMB];
__device__ __half g_Kh [MTOK * EMB];
__device__ __half g_Vh [MTOK * EMB];
__device__ __half g_ATTNh[MTOK * EMB];
__device__ __half g_X1h[MTOK * EMB];
__device__ __half g_Hh [MTOK * FFN_DIM];
// fp16 weights
__device__ __half g_WQh[EMB * EMB];
__device__ __half g_WKh[EMB * EMB];
__device__ __half g_WVh[EMB * EMB];
__device__ __half g_WOh[EMB * EMB];
__device__ __half g_W1h[FFN_DIM * EMB];
__device__ __half g_W2h[EMB * FFN_DIM];

// ---------------------------------------------------------------------------
__device__ __forceinline__ uint32_t smem_u32(const void* p) {
    uint32_t a;
    asm("{ .reg .u64 t; cvta.to.shared.u64 t, %1; cvt.u32.u64 %0, t; }" : "=r"(a) : "l"(p));
    return a;
}
__device__ __forceinline__ uint32_t f2tf32(float f) {
    uint32_t r;
    asm("cvt.rna.tf32.f32 %0, %1;" : "=r"(r) : "f"(f));
    return r;
}
__device__ __forceinline__ void mma_tf32(float* d, const uint32_t* a, const uint32_t* b) {
    asm volatile(
        "mma.sync.aligned.m16n8k8.row.col.f32.tf32.tf32.f32 "
        "{%0,%1,%2,%3}, {%4,%5,%6,%7}, {%8,%9}, {%0,%1,%2,%3};"
        : "+f"(d[0]), "+f"(d[1]), "+f"(d[2]), "+f"(d[3])
        : "r"(a[0]), "r"(a[1]), "r"(a[2]), "r"(a[3]), "r"(b[0]), "r"(b[1]));
}
__device__ __forceinline__ void mma_f16(float* d, const uint32_t* a, const uint32_t* b) {
    asm volatile(
        "mma.sync.aligned.m16n8k16.row.col.f32.f16.f16.f32 "
        "{%0,%1,%2,%3}, {%4,%5,%6,%7}, {%8,%9}, {%0,%1,%2,%3};"
        : "+f"(d[0]), "+f"(d[1]), "+f"(d[2]), "+f"(d[3])
        : "r"(a[0]), "r"(a[1]), "r"(a[2]), "r"(a[3]), "r"(b[0]), "r"(b[1]));
}
__device__ __forceinline__ void cp_async16(uint32_t dst, const void* src) {
    asm volatile("cp.async.cg.shared.global [%0], [%1], 16;" :: "r"(dst), "l"(src));
}
__device__ __forceinline__ void cp_commit() { asm volatile("cp.async.commit_group;"); }

// ---------------------------------------------------------------------------
// Round fp32 -> fp16 (elementwise)
// ---------------------------------------------------------------------------
__global__ __launch_bounds__(256) void round_f16_kernel(
    const float* __restrict__ src, __half* __restrict__ dst, int n)
{
    int i = (blockIdx.x * 256 + threadIdx.x) * 4;
    if (i < n) {
        float4 v = *(const float4*)(src + i);
        __half2 h01 = __floats2half2_rn(v.x, v.y);
        __half2 h23 = __floats2half2_rn(v.z, v.w);
        uint2 u;
        u.x = *(uint32_t*)&h01;
        u.y = *(uint32_t*)&h23;
        *(uint2*)(dst + i) = u;
    }
}

// ---------------------------------------------------------------------------
// fp16 tensor-core GEMM (mma.sync m16n8k16), 2-stage cp.async.
//   C[m,n] = sum_k A[m,k]*W[n,k] + bias[n]
//   mode 0: plain -> half out   mode 2: relu -> half out   mode 3: +res -> fp32 out
//   CTA 128x128, BK=64, 8 warps (2m x 4n), warp tile 64x32. 2 CTAs/SM.
// SMEM per stage: A[128][36] + B[128][36] uints (each uint = 2 halves)
// ---------------------------------------------------------------------------
#define GPAD 36
#define STG_OP_UINTS (128 * GPAD)
#define STG_UINTS    (2 * STG_OP_UINTS)
#define GEMM_SMEM_BYTES (2 * STG_UINTS * 4)   // 73728

__global__ __launch_bounds__(256, 2) void gemm_f16_kernel(
    const __half* __restrict__ A, const __half* __restrict__ W,
    const float* __restrict__ bias, const float* __restrict__ res,
    float* __restrict__ Cf, __half* __restrict__ Ch,
    int M, int N, int K, int mode)
{
    extern __shared__ uint32_t smg[];
    const uint32_t sbase = smem_u32(smg);

    const int tid = threadIdx.x;
    const int wid = tid >> 5;
    const int lane = tid & 31;
    const int g   = lane >> 2;
    const int tig = lane & 3;
    const int wm = wid >> 2;     // 0..1
    const int wn = wid & 3;      // 0..3
    const int m0 = blockIdx.y * 128;
    const int n0 = blockIdx.x * 128;

    const __half* Ap = A + (size_t)m0 * K;
    const __half* Wp = W + (size_t)n0 * K;

    float acc[4][4][4];
#pragma unroll
    for (int mt = 0; mt < 4; mt++)
#pragma unroll
        for (int nt = 0; nt < 4; nt++)
#pragma unroll
            for (int e = 0; e < 4; e++) acc[mt][nt][e] = 0.f;

    const int S = K >> 6;    // BK = 64 halves

    auto issue_stage = [&](int s) {
        const int buf = s & 1;
        const int k0h = s << 6;
        const uint32_t abase = sbase + (uint32_t)(buf * STG_UINTS) * 4;
        const uint32_t bbase = abase + STG_OP_UINTS * 4;
        // each operand: 128 rows x 32 uints (64 halves); 16B chunk = 4 uints
#pragma unroll
        for (int i = 0; i < 4; i++) {
            int idx = tid + 256 * i;
            int row = idx >> 3, cu = (idx & 7) << 2;
            cp_async16(abase + (uint32_t)(row * GPAD + cu) * 4,
                       Ap + (size_t)row * K + k0h + cu * 2);
            cp_async16(bbase + (uint32_t)(row * GPAD + cu) * 4,
                       Wp + (size_t)row * K + k0h + cu * 2);
        }
        cp_commit();
    };

    issue_stage(0);
    issue_stage(1);

    for (int s = 0; s < S; s++) {
        asm volatile("cp.async.wait_group 1;" ::: "memory");
        __syncthreads();     // stage s visible to all

        const int buf = s & 1;
        const uint32_t* Ab = smg + buf * STG_UINTS + (wm * 64) * GPAD;
        const uint32_t* Bb = smg + buf * STG_UINTS + STG_OP_UINTS + (wn * 32) * GPAD;
#pragma unroll
        for (int ks = 0; ks < 4; ks++) {      // 4 x k16
            uint32_t bf[4][2];
#pragma unroll
            for (int nt = 0; nt < 4; nt++) {
                const uint32_t* bp = Bb + (nt * 8 + g) * GPAD + ks * 8 + tig;
                bf[nt][0] = bp[0];
                bf[nt][1] = bp[4];
            }
#pragma unroll
            for (int mt = 0; mt < 4; mt++) {
                uint32_t af[4];
                const uint32_t* ap = Ab + (mt * 16 + g) * GPAD + ks * 8 + tig;
                af[0] = ap[0];
                af[1] = ap[8 * GPAD];
                af[2] = ap[4];
                af[3] = ap[8 * GPAD + 4];
#pragma unroll
                for (int nt = 0; nt < 4; nt++)
                    mma_f16(acc[mt][nt], af, bf[nt]);
            }
        }
        __syncthreads();     // all warps done with buffer s&1
        if (s + 2 < S) issue_stage(s + 2);
        else cp_commit();    // empty group keeps wait_group-1 invariant
    }

    // epilogue
#pragma unroll
    for (int mt = 0; mt < 4; mt++) {
        int r0 = m0 + wm * 64 + mt * 16 + g;
#pragma unroll
        for (int half = 0; half < 2; half++) {
            int m = r0 + half * 8;
#pragma unroll
            for (int nt = 0; nt < 4; nt++) {
                int n = wn * 32 + nt * 8 + tig * 2;
                float ox = acc[mt][nt][half * 2 + 0] + bias[n0 + n + 0];
                float oy = acc[mt][nt][half * 2 + 1] + bias[n0 + n + 1];
                if (mode == 3) {
                    const float* Rrow = res + (size_t)m * N + n0;
                    float2 rr = *(const float2*)(Rrow + n);
                    float2 o = make_float2(ox + rr.x, oy + rr.y);
                    *(float2*)(Cf + (size_t)m * N + n0 + n) = o;
                } else {
                    if (mode == 2) { ox = fmaxf(ox, 0.f); oy = fmaxf(oy, 0.f); }
                    *(__half2*)(Ch + (size_t)m * N + n0 + n) = __floats2half2_rn(ox, oy);
                }
            }
        }
    }
}

// ---------------------------------------------------------------------------
// Transpose (T,B,E) -> (B,T,E): exact fp32 + fp16 copy
// ---------------------------------------------------------------------------
__global__ __launch_bounds__(256) void transpose_in_kernel(const float* __restrict__ state)
{
    int m = blockIdx.x;
    int b = m / T_SEQ;
    int t = m % T_SEQ;
    float4 v = ((const float4*)(state + (size_t)t * B_SZ * EMB + (size_t)b * EMB))[threadIdx.x];
    ((float4*)(g_X0 + (size_t)m * EMB))[threadIdx.x] = v;
    __half2 h01 = __floats2half2_rn(v.x, v.y);
    __half2 h23 = __floats2half2_rn(v.z, v.w);
    uint2 u;
    u.x = *(uint32_t*)&h01;
    u.y = *(uint32_t*)&h23;
    ((uint2*)(g_X0h + (size_t)m * EMB))[threadIdx.x] = u;
}

// ---------------------------------------------------------------------------
// Flash attention, mma.sync tf32 (inputs fp16; half->float is exact in tf32).
// ---------------------------------------------------------------------------
#define AT_PAD 68
#define AT_SMEM_BYTES ((128 * AT_PAD + 64 * AT_PAD + 64 * AT_PAD + 128 * AT_PAD) * 4)

__global__ __launch_bounds__(256) void attn_mma_kernel(const uint8_t* __restrict__ mask)
{
    extern __shared__ uint32_t sma[];
    uint32_t* Qs = sma;
    uint32_t* Ks = Qs + 128 * AT_PAD;
    uint32_t* Vs = Ks + 64 * AT_PAD;
    uint32_t* Ps = Vs + 64 * AT_PAD;

    const int tq = blockIdx.x * 128;
    const int b = blockIdx.y >> 4;
    const int h = blockIdx.y & 15;
    const int tid = threadIdx.x;
    const int w = tid >> 5;
    const int lane = tid & 31;
    const int g = lane >> 2;
    const int tig = lane & 3;

    {
        const __half* Qg = g_Qh + (size_t)(b * T_SEQ + tq) * EMB + h * HD;
        for (int it = tid; it < 128 * 16; it += 256) {
            int r = it >> 4, c4 = (it & 15) * 4;
            uint2 raw = *(const uint2*)(Qg + (size_t)r * EMB + c4);
            float2 f0 = __half22float2(*(__half2*)&raw.x);
            float2 f1 = __half22float2(*(__half2*)&raw.y);
            uint32_t* d = Qs + r * AT_PAD + c4;
            d[0] = __float_as_uint(f0.x); d[1] = __float_as_uint(f0.y);
            d[2] = __float_as_uint(f1.x); d[3] = __float_as_uint(f1.y);
        }
    }
    __syncthreads();

    uint32_t qf[8][4];
    {
        const uint32_t* base = Qs + (w * 16 + g) * AT_PAD;
#pragma unroll
        for (int ks = 0; ks < 8; ks++) {
            qf[ks][0] = base[ks * 8 + tig];
            qf[ks][1] = base[8 * AT_PAD + ks * 8 + tig];
            qf[ks][2] = base[ks * 8 + tig + 4];
            qf[ks][3] = base[8 * AT_PAD + ks * 8 + tig + 4];
        }
    }

    float oacc[8][4];
#pragma unroll
    for (int nt = 0; nt < 8; nt++)
#pragma unroll
        for (int e = 0; e < 4; e++) oacc[nt][e] = 0.f;
    float mrow[2] = { -1e30f, -1e30f };
    float lrow[2] = { 0.f, 0.f };

    const uint8_t* mb = mask + (size_t)b * T_SEQ;

    for (int kt = 0; kt < T_SEQ; kt += 64) {
        __syncthreads();
        {
            const __half* Kg = g_Kh + (size_t)(b * T_SEQ + kt) * EMB + h * HD;
            const __half* Vg = g_Vh + (size_t)(b * T_SEQ + kt) * EMB + h * HD;
            for (int it = tid; it < 64 * 16; it += 256) {
                int r = it >> 4, c4 = (it & 15) * 4;
                uint2 kr = *(const uint2*)(Kg + (size_t)r * EMB + c4);
                float2 k0 = __half22float2(*(__half2*)&kr.x);
                float2 k1 = __half22float2(*(__half2*)&kr.y);
                uint32_t* dk = Ks + r * AT_PAD + c4;
                dk[0] = __float_as_uint(k0.x); dk[1] = __float_as_uint(k0.y);
                dk[2] = __float_as_uint(k1.x); dk[3] = __float_as_uint(k1.y);
                uint2 vr = *(const uint2*)(Vg + (size_t)r * EMB + c4);
                float2 v0 = __half22float2(*(__half2*)&vr.x);
                float2 v1 = __half22float2(*(__half2*)&vr.y);
                uint32_t* dv = Vs + r * AT_PAD + c4;
                dv[0] = __float_as_uint(v0.x); dv[1] = __float_as_uint(v0.y);
                dv[2] = __float_as_uint(v1.x); dv[3] = __float_as_uint(v1.y);
            }
        }
        __syncthreads();

        float sacc[8][4];
#pragma unroll
        for (int nt = 0; nt < 8; nt++)
#pragma unroll
            for (int e = 0; e < 4; e++) sacc[nt][e] = 0.f;

#pragma unroll
        for (int ks = 0; ks < 8; ks++) {
#pragma unroll
            for (int nt = 0; nt < 8; nt++) {
                uint32_t bf[2];
                const uint32_t* kp = Ks + (nt * 8 + g) * AT_PAD + ks * 8 + tig;
                bf[0] = kp[0];
                bf[1] = kp[4];
                mma_tf32(sacc[nt], qf[ks], bf);
            }
        }

#pragma unroll
        for (int nt = 0; nt < 8; nt++) {
            bool m0 = mb[kt + nt * 8 + 2 * tig] != 0;
            bool m1 = mb[kt + nt * 8 + 2 * tig + 1] != 0;
            sacc[nt][0] = m0 ? -1e30f : sacc[nt][0] * 0.125f;
            sacc[nt][1] = m1 ? -1e30f : sacc[nt][1] * 0.125f;
            sacc[nt][2] = m0 ? -1e30f : sacc[nt][2] * 0.125f;
            sacc[nt][3] = m1 ? -1e30f : sacc[nt][3] * 0.125f;
        }

#pragma unroll
        for (int half = 0; half < 2; half++) {
            float mx = -1e30f;
#pragma unroll
            for (int nt = 0; nt < 8; nt++) {
                mx = fmaxf(mx, sacc[nt][2 * half + 0]);
                mx = fmaxf(mx, sacc[nt][2 * half + 1]);
            }
            mx = fmaxf(mx, __shfl_xor_sync(0xffffffffu, mx, 1));
            mx = fmaxf(mx, __shfl_xor_sync(0xffffffffu, mx, 2));
            float mn = fmaxf(mrow[half], mx);
            float alpha = __expf(mrow[half] - mn);
            mrow[half] = mn;
            float rs = 0.f;
            uint32_t* prow = Ps + (w * 16 + g + half * 8) * AT_PAD;
#pragma unroll
            for (int nt = 0; nt < 8; nt++) {
                float p0 = __expf(sacc[nt][2 * half + 0] - mn);
                float p1 = __expf(sacc[nt][2 * half + 1] - mn);
                rs += p0 + p1;
                prow[nt * 8 + 2 * tig + 0] = f2tf32(p0);
                prow[nt * 8 + 2 * tig + 1] = f2tf32(p1);
            }
            rs += __shfl_xor_sync(0xffffffffu, rs, 1);
            rs += __shfl_xor_sync(0xffffffffu, rs, 2);
            lrow[half] = lrow[half] * alpha + rs;
#pragma unroll
            for (int nt = 0; nt < 8; nt++) {
                oacc[nt][2 * half + 0] *= alpha;
                oacc[nt][2 * half + 1] *= alpha;
            }
        }
        __syncwarp();

#pragma unroll
        for (int ks = 0; ks < 8; ks++) {
            uint32_t af[4];
            const uint32_t* pp = Ps + (w * 16 + g) * AT_PAD + ks * 8 + tig;
            af[0] = pp[0];
            af[1] = pp[8 * AT_PAD];
            af[2] = pp[4];
            af[3] = pp[8 * AT_PAD + 4];
#pragma unroll
            for (int nt = 0; nt < 8; nt++) {
                uint32_t bf[2];
                const uint32_t* vp = Vs + (ks * 8 + tig) * AT_PAD + nt * 8 + g;
                bf[0] = vp[0];
                bf[1] = vp[4 * AT_PAD];
                mma_tf32(oacc[nt], af, bf);
            }
        }
        __syncwarp();
    }

    // write fp16 output (consumed only by out-proj GEMM)
#pragma unroll
    for (int half = 0; half < 2; half++) {
        float inv = 1.f / lrow[half];
        int r = tq + w * 16 + g + half * 8;
        __half* dst = g_ATTNh + (size_t)(b * T_SEQ + r) * EMB + h * HD;
#pragma unroll
        for (int nt = 0; nt < 8; nt++) {
            *(__half2*)(dst + nt * 8 + 2 * tig) =
                __floats2half2_rn(oacc[nt][2 * half + 0] * inv,
                                  oacc[nt][2 * half + 1] * inv);
        }
    }
}

// ---------------------------------------------------------------------------
// LayerNorm (E=1024). Optionally writes an fp16 copy.
// ---------------------------------------------------------------------------
__global__ __launch_bounds__(256) void ln_kernel(
    const float* __restrict__ X, const float* __restrict__ gw,
    const float* __restrict__ bw, float* __restrict__ out,
    __half* __restrict__ out_h, int transposed)
{
    int m = blockIdx.x;
    float4 v = ((const float4*)(X + (size_t)m * EMB))[threadIdx.x];
    float s = v.x + v.y + v.z + v.w;
    float sq = v.x * v.x + v.y * v.y + v.z * v.z + v.w * v.w;

    __shared__ float rs[256], rq[256];
    rs[threadIdx.x] = s; rq[threadIdx.x] = sq;
    __syncthreads();
    for (int st = 128; st > 0; st >>= 1) {
        if (threadIdx.x < st) {
            rs[threadIdx.x] += rs[threadIdx.x + st];
            rq[threadIdx.x] += rq[threadIdx.x + st];
        }
        __syncthreads();
    }
    float mu  = rs[0] * (1.f / EMB);
    float var = rq[0] * (1.f / EMB) - mu * mu;
    float inv = rsqrtf(var + 1e-5f);

    float4 g4 = ((const float4*)gw)[threadIdx.x];
    float4 b4 = ((const float4*)bw)[threadIdx.x];
    float4 o;
    o.x = (v.x - mu) * inv * g4.x + b4.x;
    o.y = (v.y - mu) * inv * g4.y + b4.y;
    o.z = (v.z - mu) * inv * g4.z + b4.z;
    o.w = (v.w - mu) * inv * g4.w + b4.w;

    size_t obase;
    if (transposed) {
        int b = m / T_SEQ, t = m % T_SEQ;
        obase = (size_t)t * B_SZ * EMB + (size_t)b * EMB;
    } else {
        obase = (size_t)m * EMB;
    }
    ((float4*)(out + obase))[threadIdx.x] = o;
    if (out_h) {
        __half2 h01 = __floats2half2_rn(o.x, o.y);
        __half2 h23 = __floats2half2_rn(o.z, o.w);
        uint2 u;
        u.x = *(uint32_t*)&h01;
        u.y = *(uint32_t*)&h23;
        ((uint2*)(out_h + (size_t)m * EMB))[threadIdx.x] = u;
    }
}

// ---------------------------------------------------------------------------
extern "C" void kernel_launch(void* const* d_in, const int* in_sizes, int n_in,
                              void* d_out, int out_size)
{
    const float*   state = (const float*)d_in[0];
    const uint8_t* mask  = (const uint8_t*)d_in[1];
    const float* q_w  = (const float*)d_in[2];
    const float* q_b  = (const float*)d_in[3];
    const float* k_w  = (const float*)d_in[4];
    const float* k_b  = (const float*)d_in[5];
    const float* v_w  = (const float*)d_in[6];
    const float* v_b  = (const float*)d_in[7];
    const float* out_w = (const float*)d_in[8];
    const float* out_b = (const float*)d_in[9];
    const float* ln1_g = (const float*)d_in[10];
    const float* ln1_b = (const float*)d_in[11];
    const float* fc1_w = (const float*)d_in[12];
    const float* fc1_b = (const float*)d_in[13];
    const float* fc2_w = (const float*)d_in[14];
    const float* fc2_b = (const float*)d_in[15];
    const float* ln2_g = (const float*)d_in[16];
    const float* ln2_b = (const float*)d_in[17];
    float* out = (float*)d_out;

    float *pX0, *pY, *pX1;
    __half *pX0h, *pQh, *pKh, *pVh, *pATTNh, *pX1h, *pHh;
    __half *pWQ, *pWK, *pWV, *pWO, *pW1, *pW2;
    cudaGetSymbolAddress((void**)&pX0,    g_X0);
    cudaGetSymbolAddress((void**)&pY,     g_Y);
    cudaGetSymbolAddress((void**)&pX1,    g_X1);
    cudaGetSymbolAddress((void**)&pX0h,   g_X0h);
    cudaGetSymbolAddress((void**)&pQh,    g_Qh);
    cudaGetSymbolAddress((void**)&pKh,    g_Kh);
    cudaGetSymbolAddress((void**)&pVh,    g_Vh);
    cudaGetSymbolAddress((void**)&pATTNh, g_ATTNh);
    cudaGetSymbolAddress((void**)&pX1h,   g_X1h);
    cudaGetSymbolAddress((void**)&pHh,    g_Hh);
    cudaGetSymbolAddress((void**)&pWQ,    g_WQh);
    cudaGetSymbolAddress((void**)&pWK,    g_WKh);
    cudaGetSymbolAddress((void**)&pWV,    g_WVh);
    cudaGetSymbolAddress((void**)&pWO,    g_WOh);
    cudaGetSymbolAddress((void**)&pW1,    g_W1h);
    cudaGetSymbolAddress((void**)&pW2,    g_W2h);

    cudaFuncSetAttribute(attn_mma_kernel, cudaFuncAttributeMaxDynamicSharedMemorySize,
                         AT_SMEM_BYTES);
    cudaFuncSetAttribute(gemm_f16_kernel, cudaFuncAttributeMaxDynamicSharedMemorySize,
                         GEMM_SMEM_BYTES);

    // 0. round weights to fp16 + transpose input (exact + fp16)
    const int NW1 = EMB * EMB;
    round_f16_kernel<<<NW1 / 1024, 256>>>(q_w,  pWQ, NW1);
    round_f16_kernel<<<NW1 / 1024, 256>>>(k_w,  pWK, NW1);
    round_f16_kernel<<<NW1 / 1024, 256>>>(v_w,  pWV, NW1);
    round_f16_kernel<<<NW1 / 1024, 256>>>(out_w, pWO, NW1);
    round_f16_kernel<<<FFN_DIM * EMB / 1024, 256>>>(fc1_w, pW1, FFN_DIM * EMB);
    round_f16_kernel<<<EMB * FFN_DIM / 1024, 256>>>(fc2_w, pW2, EMB * FFN_DIM);
    transpose_in_kernel<<<MTOK, 256>>>(state);

    // 1. QKV projections (fp16 out)
    dim3 gProj(EMB / 128, MTOK / 128);
    gemm_f16_kernel<<<gProj, 256, GEMM_SMEM_BYTES>>>(pX0h, pWQ, q_b, nullptr, nullptr, pQh, MTOK, EMB, EMB, 0);
    gemm_f16_kernel<<<gProj, 256, GEMM_SMEM_BYTES>>>(pX0h, pWK, k_b, nullptr, nullptr, pKh, MTOK, EMB, EMB, 0);
    gemm_f16_kernel<<<gProj, 256, GEMM_SMEM_BYTES>>>(pX0h, pWV, v_b, nullptr, nullptr, pVh, MTOK, EMB, EMB, 0);

    // 2. attention
    dim3 gAttn(T_SEQ / 128, B_SZ * NHEADS);
    attn_mma_kernel<<<gAttn, 256, AT_SMEM_BYTES>>>(mask);

    // 3. out projection + residual(X0 exact) -> fp32
    gemm_f16_kernel<<<gProj, 256, GEMM_SMEM_BYTES>>>(pATTNh, pWO, out_b, pX0, pY, nullptr, MTOK, EMB, EMB, 3);

    // 4. LN1 -> X1 exact + X1h fp16
    ln_kernel<<<MTOK, 256>>>(pY, ln1_g, ln1_b, pX1, pX1h, 0);

    // 5. fc1 + relu -> fp16 H
    dim3 gFc1(FFN_DIM / 128, MTOK / 128);
    gemm_f16_kernel<<<gFc1, 256, GEMM_SMEM_BYTES>>>(pX1h, pW1, fc1_b, nullptr, nullptr, pHh, MTOK, FFN_DIM, EMB, 2);

    // 6. fc2 + residual(X1 exact) -> fp32
    gemm_f16_kernel<<<gProj, 256, GEMM_SMEM_BYTES>>>(pHh, pW2, fc2_b, pX1, pY, nullptr, MTOK, EMB, FFN_DIM, 3);

    // 7. LN2 -> output (T,B,E)
    ln_kernel<<<MTOK, 256>>>(pY, ln2_g, ln2_b, out, nullptr, 1);
}

// round 8
// speedup vs baseline: 6.1944x; 1.1965x over previous
#include <cuda_runtime.h>
#include <cuda_fp16.h>
#include <math.h>
#include <stdint.h>

// Problem constants
#define T_SEQ 2048
#define B_SZ  4
#define EMB   1024
#define NHEADS 16
#define HD    64
#define FFN_DIM 4096
#define MTOK  (T_SEQ * B_SZ)   // 8192 tokens
#define E3    (3 * EMB)

// ---------------- scratch (device globals; no cudaMalloc allowed) ----------
__device__ float  g_X0 [MTOK * EMB];      // exact token-major input (residual)
__device__ float  g_Y  [MTOK * EMB];      // pre-LN sum
__device__ float  g_X1 [MTOK * EMB];      // exact LN1 out (residual)
__device__ __half g_X0h[MTOK * EMB];      // fp16 GEMM operands
__device__ __half g_QKVh[MTOK * E3];      // fused QKV output [tok][3*EMB]
__device__ __half g_ATTNh[MTOK * EMB];
__device__ __half g_X1h[MTOK * EMB];
__device__ __half g_Hh [MTOK * FFN_DIM];
// fp16 weights
__device__ __half g_WQKVh[E3 * EMB];      // rows: q(0..1023), k(1024..2047), v(2048..3071)
__device__ float  g_BQKV [E3];
__device__ __half g_WOh[EMB * EMB];
__device__ __half g_W1h[FFN_DIM * EMB];
__device__ __half g_W2h[EMB * FFN_DIM];

// ---------------------------------------------------------------------------
__device__ __forceinline__ uint32_t smem_u32(const void* p) {
    uint32_t a;
    asm("{ .reg .u64 t; cvta.to.shared.u64 t, %1; cvt.u32.u64 %0, t; }" : "=r"(a) : "l"(p));
    return a;
}
__device__ __forceinline__ void mma_f16(float* d, const uint32_t* a, const uint32_t* b) {
    asm volatile(
        "mma.sync.aligned.m16n8k16.row.col.f32.f16.f16.f32 "
        "{%0,%1,%2,%3}, {%4,%5,%6,%7}, {%8,%9}, {%0,%1,%2,%3};"
        : "+f"(d[0]), "+f"(d[1]), "+f"(d[2]), "+f"(d[3])
        : "r"(a[0]), "r"(a[1]), "r"(a[2]), "r"(a[3]), "r"(b[0]), "r"(b[1]));
}
__device__ __forceinline__ void cp_async16(uint32_t dst, const void* src) {
    asm volatile("cp.async.cg.shared.global [%0], [%1], 16;" :: "r"(dst), "l"(src));
}
__device__ __forceinline__ void cp_commit() { asm volatile("cp.async.commit_group;"); }

// ---------------------------------------------------------------------------
// Round fp32 -> fp16 (elementwise)
// ---------------------------------------------------------------------------
__global__ __launch_bounds__(256) void round_f16_kernel(
    const float* __restrict__ src, __half* __restrict__ dst, int n)
{
    int i = (blockIdx.x * 256 + threadIdx.x) * 4;
    if (i < n) {
        float4 v = *(const float4*)(src + i);
        __half2 h01 = __floats2half2_rn(v.x, v.y);
        __half2 h23 = __floats2half2_rn(v.z, v.w);
        uint2 u;
        u.x = *(uint32_t*)&h01;
        u.y = *(uint32_t*)&h23;
        *(uint2*)(dst + i) = u;
    }
}
__global__ __launch_bounds__(256) void copy_f32_kernel(
    const float* __restrict__ src, float* __restrict__ dst, int n)
{
    int i = blockIdx.x * 256 + threadIdx.x;
    if (i < n) dst[i] = src[i];
}

// ---------------------------------------------------------------------------
// fp16 tensor-core GEMM (mma.sync m16n8k16), 2-stage cp.async.
//   mode 0: plain -> half out   mode 2: relu -> half out   mode 3: +res -> fp32 out
//   CTA 128x128, BK=64, 8 warps (2m x 4n), warp tile 64x32. 2 CTAs/SM.
// ---------------------------------------------------------------------------
#define GPAD 36
#define STG_OP_UINTS (128 * GPAD)
#define STG_UINTS    (2 * STG_OP_UINTS)
#define GEMM_SMEM_BYTES (2 * STG_UINTS * 4)   // 73728

__global__ __launch_bounds__(256, 2) void gemm_f16_kernel(
    const __half* __restrict__ A, const __half* __restrict__ W,
    const float* __restrict__ bias, const float* __restrict__ res,
    float* __restrict__ Cf, __half* __restrict__ Ch,
    int M, int N, int K, int mode)
{
    extern __shared__ uint32_t smg[];
    const uint32_t sbase = smem_u32(smg);

    const int tid = threadIdx.x;
    const int wid = tid >> 5;
    const int lane = tid & 31;
    const int g   = lane >> 2;
    const int tig = lane & 3;
    const int wm = wid >> 2;
    const int wn = wid & 3;
    const int m0 = blockIdx.y * 128;
    const int n0 = blockIdx.x * 128;

    const __half* Ap = A + (size_t)m0 * K;
    const __half* Wp = W + (size_t)n0 * K;

    float acc[4][4][4];
#pragma unroll
    for (int mt = 0; mt < 4; mt++)
#pragma unroll
        for (int nt = 0; nt < 4; nt++)
#pragma unroll
            for (int e = 0; e < 4; e++) acc[mt][nt][e] = 0.f;

    const int S = K >> 6;

    auto issue_stage = [&](int s) {
        const int buf = s & 1;
        const int k0h = s << 6;
        const uint32_t abase = sbase + (uint32_t)(buf * STG_UINTS) * 4;
        const uint32_t bbase = abase + STG_OP_UINTS * 4;
#pragma unroll
        for (int i = 0; i < 4; i++) {
            int idx = tid + 256 * i;
            int row = idx >> 3, cu = (idx & 7) << 2;
            cp_async16(abase + (uint32_t)(row * GPAD + cu) * 4,
                       Ap + (size_t)row * K + k0h + cu * 2);
            cp_async16(bbase + (uint32_t)(row * GPAD + cu) * 4,
                       Wp + (size_t)row * K + k0h + cu * 2);
        }
        cp_commit();
    };

    issue_stage(0);
    issue_stage(1);

    for (int s = 0; s < S; s++) {
        asm volatile("cp.async.wait_group 1;" ::: "memory");
        __syncthreads();

        const int buf = s & 1;
        const uint32_t* Ab = smg + buf * STG_UINTS + (wm * 64) * GPAD;
        const uint32_t* Bb = smg + buf * STG_UINTS + STG_OP_UINTS + (wn * 32) * GPAD;
#pragma unroll
        for (int ks = 0; ks < 4; ks++) {
            uint32_t bf[4][2];
#pragma unroll
            for (int nt = 0; nt < 4; nt++) {
                const uint32_t* bp = Bb + (nt * 8 + g) * GPAD + ks * 8 + tig;
                bf[nt][0] = bp[0];
                bf[nt][1] = bp[4];
            }
#pragma unroll
            for (int mt = 0; mt < 4; mt++) {
                uint32_t af[4];
                const uint32_t* ap = Ab + (mt * 16 + g) * GPAD + ks * 8 + tig;
                af[0] = ap[0];
                af[1] = ap[8 * GPAD];
                af[2] = ap[4];
                af[3] = ap[8 * GPAD + 4];
#pragma unroll
                for (int nt = 0; nt < 4; nt++)
                    mma_f16(acc[mt][nt], af, bf[nt]);
            }
        }
        __syncthreads();
        if (s + 2 < S) issue_stage(s + 2);
        else cp_commit();
    }

    // epilogue
#pragma unroll
    for (int mt = 0; mt < 4; mt++) {
        int r0 = m0 + wm * 64 + mt * 16 + g;
#pragma unroll
        for (int half = 0; half < 2; half++) {
            int m = r0 + half * 8;
#pragma unroll
            for (int nt = 0; nt < 4; nt++) {
                int n = wn * 32 + nt * 8 + tig * 2;
                float ox = acc[mt][nt][half * 2 + 0] + bias[n0 + n + 0];
                float oy = acc[mt][nt][half * 2 + 1] + bias[n0 + n + 1];
                if (mode == 3) {
                    const float* Rrow = res + (size_t)m * N + n0;
                    float2 rr = *(const float2*)(Rrow + n);
                    *(float2*)(Cf + (size_t)m * N + n0 + n) = make_float2(ox + rr.x, oy + rr.y);
                } else {
                    if (mode == 2) { ox = fmaxf(ox, 0.f); oy = fmaxf(oy, 0.f); }
                    *(__half2*)(Ch + (size_t)m * N + n0 + n) = __floats2half2_rn(ox, oy);
                }
            }
        }
    }
}

// ---------------------------------------------------------------------------
// Transpose (T,B,E) -> (B,T,E): exact fp32 + fp16 copy
// ---------------------------------------------------------------------------
__global__ __launch_bounds__(256) void transpose_in_kernel(const float* __restrict__ state)
{
    int m = blockIdx.x;
    int b = m / T_SEQ;
    int t = m % T_SEQ;
    float4 v = ((const float4*)(state + (size_t)t * B_SZ * EMB + (size_t)b * EMB))[threadIdx.x];
    ((float4*)(g_X0 + (size_t)m * EMB))[threadIdx.x] = v;
    __half2 h01 = __floats2half2_rn(v.x, v.y);
    __half2 h23 = __floats2half2_rn(v.z, v.w);
    uint2 u;
    u.x = *(uint32_t*)&h01;
    u.y = *(uint32_t*)&h23;
    ((uint2*)(g_X0h + (size_t)m * EMB))[threadIdx.x] = u;
}

// ---------------------------------------------------------------------------
// Flash attention, full fp16 mma (m16n8k16).
//   grid (T/128, B*H), 256 thr = 8 warps; warp w owns q-rows w*16..+15.
//   Q/K/V read from fused QKV buffer (row stride 3*EMB).
//   V stored transposed in smem (Vt[d][kv]) so PV's B operand is kv-major.
// SMEM uints: Qs[128][36], Ks[64][36], Vt[64][36], Ps[128][36]
// ---------------------------------------------------------------------------
#define APADU 36                       // uints per row (64 halves + pad)
#define AT_SMEM_BYTES ((128 * APADU + 64 * APADU + 64 * APADU + 128 * APADU) * 4)

__global__ __launch_bounds__(256, 2) void attn_mma_kernel(const uint8_t* __restrict__ mask)
{
    extern __shared__ uint32_t sma[];
    uint32_t* Qs = sma;
    uint32_t* Ks = Qs + 128 * APADU;
    uint32_t* Vt = Ks + 64 * APADU;
    uint32_t* Ps = Vt + 64 * APADU;

    const int tq = blockIdx.x * 128;
    const int b = blockIdx.y >> 4;
    const int h = blockIdx.y & 15;
    const int tid = threadIdx.x;
    const int w = tid >> 5;
    const int lane = tid & 31;
    const int g = lane >> 2;
    const int tig = lane & 3;

    // fill Q tile (fp16, direct copy)
    {
        const __half* Qg = g_QKVh + (size_t)(b * T_SEQ + tq) * E3 + h * HD;
        for (int it = tid; it < 128 * 16; it += 256) {
            int r = it >> 4, c4 = (it & 15) * 4;          // half index
            uint2 raw = *(const uint2*)(Qg + (size_t)r * E3 + c4);
            *(uint2*)(Qs + r * APADU + (c4 >> 1)) = raw;
        }
    }
    __syncthreads();

    // hoist Q fragments: 4 k16-steps over d=64
    uint32_t qf[4][4];
    {
        const uint32_t* base = Qs + (w * 16 + g) * APADU;
#pragma unroll
        for (int ks = 0; ks < 4; ks++) {
            qf[ks][0] = base[ks * 8 + tig];
            qf[ks][1] = base[8 * APADU + ks * 8 + tig];
            qf[ks][2] = base[ks * 8 + tig + 4];
            qf[ks][3] = base[8 * APADU + ks * 8 + tig + 4];
        }
    }

    float oacc[8][4];
#pragma unroll
    for (int nt = 0; nt < 8; nt++)
#pragma unroll
        for (int e = 0; e < 4; e++) oacc[nt][e] = 0.f;
    float mrow[2] = { -1e30f, -1e30f };
    float lrow[2] = { 0.f, 0.f };

    const uint8_t* mb = mask + (size_t)b * T_SEQ;
    __half* Vth = (__half*)Vt;

    for (int kt = 0; kt < T_SEQ; kt += 64) {
        __syncthreads();
        {
            const __half* Kg = g_QKVh + (size_t)(b * T_SEQ + kt) * E3 + EMB + h * HD;
            const __half* Vg = g_QKVh + (size_t)(b * T_SEQ + kt) * E3 + 2 * EMB + h * HD;
            for (int it = tid; it < 64 * 16; it += 256) {
                int r = it >> 4, c4 = (it & 15) * 4;
                uint2 kr = *(const uint2*)(Kg + (size_t)r * E3 + c4);
                *(uint2*)(Ks + r * APADU + (c4 >> 1)) = kr;
                // V transposed: Vt[d][kv] halves
                uint2 vr = *(const uint2*)(Vg + (size_t)r * E3 + c4);
                __half2 v01 = *(__half2*)&vr.x;
                __half2 v23 = *(__half2*)&vr.y;
                Vth[(c4 + 0) * (2 * APADU) + r] = __low2half(v01);
                Vth[(c4 + 1) * (2 * APADU) + r] = __high2half(v01);
                Vth[(c4 + 2) * (2 * APADU) + r] = __low2half(v23);
                Vth[(c4 + 3) * (2 * APADU) + r] = __high2half(v23);
            }
        }
        __syncthreads();

        // S = Q K^T : warp computes 16 x 64 (8 n-tiles), k-depth 64 (4 k16)
        float sacc[8][4];
#pragma unroll
        for (int nt = 0; nt < 8; nt++)
#pragma unroll
            for (int e = 0; e < 4; e++) sacc[nt][e] = 0.f;

#pragma unroll
        for (int ks = 0; ks < 4; ks++) {
#pragma unroll
            for (int nt = 0; nt < 8; nt++) {
                uint32_t bf[2];
                const uint32_t* kp = Ks + (nt * 8 + g) * APADU + ks * 8 + tig;
                bf[0] = kp[0];
                bf[1] = kp[4];
                mma_f16(sacc[nt], qf[ks], bf);
            }
        }

        // scale + mask
#pragma unroll
        for (int nt = 0; nt < 8; nt++) {
            bool m0 = mb[kt + nt * 8 + 2 * tig] != 0;
            bool m1 = mb[kt + nt * 8 + 2 * tig + 1] != 0;
            sacc[nt][0] = m0 ? -1e30f : sacc[nt][0] * 0.125f;
            sacc[nt][1] = m1 ? -1e30f : sacc[nt][1] * 0.125f;
            sacc[nt][2] = m0 ? -1e30f : sacc[nt][2] * 0.125f;
            sacc[nt][3] = m1 ? -1e30f : sacc[nt][3] * 0.125f;
        }

        // online softmax per row-half; write P (fp16) to warp-private rows
#pragma unroll
        for (int half = 0; half < 2; half++) {
            float mx = -1e30f;
#pragma unroll
            for (int nt = 0; nt < 8; nt++) {
                mx = fmaxf(mx, sacc[nt][2 * half + 0]);
                mx = fmaxf(mx, sacc[nt][2 * half + 1]);
            }
            mx = fmaxf(mx, __shfl_xor_sync(0xffffffffu, mx, 1));
            mx = fmaxf(mx, __shfl_xor_sync(0xffffffffu, mx, 2));
            float mn = fmaxf(mrow[half], mx);
            float alpha = __expf(mrow[half] - mn);
            mrow[half] = mn;
            float rs = 0.f;
            __half* prow = (__half*)(Ps + (w * 16 + g + half * 8) * APADU);
#pragma unroll
            for (int nt = 0; nt < 8; nt++) {
                float p0 = __expf(sacc[nt][2 * half + 0] - mn);
                float p1 = __expf(sacc[nt][2 * half + 1] - mn);
                rs += p0 + p1;
                *(__half2*)(prow + nt * 8 + 2 * tig) = __floats2half2_rn(p0, p1);
            }
            rs += __shfl_xor_sync(0xffffffffu, rs, 1);
            rs += __shfl_xor_sync(0xffffffffu, rs, 2);
            lrow[half] = lrow[half] * alpha + rs;
#pragma unroll
            for (int nt = 0; nt < 8; nt++) {
                oacc[nt][2 * half + 0] *= alpha;
                oacc[nt][2 * half + 1] *= alpha;
            }
        }
        __syncwarp();

        // O += P Vt : k-depth 64 (kv), 8 d-tiles
#pragma unroll
        for (int ks = 0; ks < 4; ks++) {
            uint32_t af[4];
            const uint32_t* pp = Ps + (w * 16 + g) * APADU + ks * 8 + tig;
            af[0] = pp[0];
            af[1] = pp[8 * APADU];
            af[2] = pp[4];
            af[3] = pp[8 * APADU + 4];
#pragma unroll
            for (int nt = 0; nt < 8; nt++) {
                uint32_t bf[2];
                const uint32_t* vp = Vt + (nt * 8 + g) * APADU + ks * 8 + tig;
                bf[0] = vp[0];
                bf[1] = vp[4];
                mma_f16(oacc[nt], af, bf);
            }
        }
        __syncwarp();
    }

    // write fp16 output
#pragma unroll
    for (int half = 0; half < 2; half++) {
        float inv = 1.f / lrow[half];
        int r = tq + w * 16 + g + half * 8;
        __half* dst = g_ATTNh + (size_t)(b * T_SEQ + r) * EMB + h * HD;
#pragma unroll
        for (int nt = 0; nt < 8; nt++) {
            *(__half2*)(dst + nt * 8 + 2 * tig) =
                __floats2half2_rn(oacc[nt][2 * half + 0] * inv,
                                  oacc[nt][2 * half + 1] * inv);
        }
    }
}

// ---------------------------------------------------------------------------
// LayerNorm (E=1024). Optionally writes an fp16 copy.
// ---------------------------------------------------------------------------
__global__ __launch_bounds__(256) void ln_kernel(
    const float* __restrict__ X, const float* __restrict__ gw,
    const float* __restrict__ bw, float* __restrict__ out,
    __half* __restrict__ out_h, int transposed)
{
    int m = blockIdx.x;
    float4 v = ((const float4*)(X + (size_t)m * EMB))[threadIdx.x];
    float s = v.x + v.y + v.z + v.w;
    float sq = v.x * v.x + v.y * v.y + v.z * v.z + v.w * v.w;

    __shared__ float rs[256], rq[256];
    rs[threadIdx.x] = s; rq[threadIdx.x] = sq;
    __syncthreads();
    for (int st = 128; st > 0; st >>= 1) {
        if (threadIdx.x < st) {
            rs[threadIdx.x] += rs[threadIdx.x + st];
            rq[threadIdx.x] += rq[threadIdx.x + st];
        }
        __syncthreads();
    }
    float mu  = rs[0] * (1.f / EMB);
    float var = rq[0] * (1.f / EMB) - mu * mu;
    float inv = rsqrtf(var + 1e-5f);

    float4 g4 = ((const float4*)gw)[threadIdx.x];
    float4 b4 = ((const float4*)bw)[threadIdx.x];
    float4 o;
    o.x = (v.x - mu) * inv * g4.x + b4.x;
    o.y = (v.y - mu) * inv * g4.y + b4.y;
    o.z = (v.z - mu) * inv * g4.z + b4.z;
    o.w = (v.w - mu) * inv * g4.w + b4.w;

    size_t obase;
    if (transposed) {
        int b = m / T_SEQ, t = m % T_SEQ;
        obase = (size_t)t * B_SZ * EMB + (size_t)b * EMB;
    } else {
        obase = (size_t)m * EMB;
    }
    ((float4*)(out + obase))[threadIdx.x] = o;
    if (out_h) {
        __half2 h01 = __floats2half2_rn(o.x, o.y);
        __half2 h23 = __floats2half2_rn(o.z, o.w);
        uint2 u;
        u.x = *(uint32_t*)&h01;
        u.y = *(uint32_t*)&h23;
        ((uint2*)(out_h + (size_t)m * EMB))[threadIdx.x] = u;
    }
}

// ---------------------------------------------------------------------------
extern "C" void kernel_launch(void* const* d_in, const int* in_sizes, int n_in,
                              void* d_out, int out_size)
{
    const float*   state = (const float*)d_in[0];
    const uint8_t* mask  = (const uint8_t*)d_in[1];
    const float* q_w  = (const float*)d_in[2];
    const float* q_b  = (const float*)d_in[3];
    const float* k_w  = (const float*)d_in[4];
    const float* k_b  = (const float*)d_in[5];
    const float* v_w  = (const float*)d_in[6];
    const float* v_b  = (const float*)d_in[7];
    const float* out_w = (const float*)d_in[8];
    const float* out_b = (const float*)d_in[9];
    const float* ln1_g = (const float*)d_in[10];
    const float* ln1_b = (const float*)d_in[11];
    const float* fc1_w = (const float*)d_in[12];
    const float* fc1_b = (const float*)d_in[13];
    const float* fc2_w = (const float*)d_in[14];
    const float* fc2_b = (const float*)d_in[15];
    const float* ln2_g = (const float*)d_in[16];
    const float* ln2_b = (const float*)d_in[17];
    float* out = (float*)d_out;

    float *pX0, *pY, *pX1, *pBQKV;
    __half *pX0h, *pQKVh, *pATTNh, *pX1h, *pHh;
    __half *pWQKV, *pWO, *pW1, *pW2;
    cudaGetSymbolAddress((void**)&pX0,    g_X0);
    cudaGetSymbolAddress((void**)&pY,     g_Y);
    cudaGetSymbolAddress((void**)&pX1,    g_X1);
    cudaGetSymbolAddress((void**)&pX0h,   g_X0h);
    cudaGetSymbolAddress((void**)&pQKVh,  g_QKVh);
    cudaGetSymbolAddress((void**)&pATTNh, g_ATTNh);
    cudaGetSymbolAddress((void**)&pX1h,   g_X1h);
    cudaGetSymbolAddress((void**)&pHh,    g_Hh);
    cudaGetSymbolAddress((void**)&pWQKV,  g_WQKVh);
    cudaGetSymbolAddress((void**)&pBQKV,  g_BQKV);
    cudaGetSymbolAddress((void**)&pWO,    g_WOh);
    cudaGetSymbolAddress((void**)&pW1,    g_W1h);
    cudaGetSymbolAddress((void**)&pW2,    g_W2h);

    cudaFuncSetAttribute(attn_mma_kernel, cudaFuncAttributeMaxDynamicSharedMemorySize,
                         AT_SMEM_BYTES);
    cudaFuncSetAttribute(gemm_f16_kernel, cudaFuncAttributeMaxDynamicSharedMemorySize,
                         GEMM_SMEM_BYTES);

    // 0. round weights to fp16 (QKV fused) + concat biases + transpose input
    const int NW1 = EMB * EMB;
    round_f16_kernel<<<NW1 / 1024, 256>>>(q_w,  pWQKV,           NW1);
    round_f16_kernel<<<NW1 / 1024, 256>>>(k_w,  pWQKV + NW1,     NW1);
    round_f16_kernel<<<NW1 / 1024, 256>>>(v_w,  pWQKV + 2 * NW1, NW1);
    copy_f32_kernel<<<EMB / 256, 256>>>(q_b, pBQKV,           EMB);
    copy_f32_kernel<<<EMB / 256, 256>>>(k_b, pBQKV + EMB,     EMB);
    copy_f32_kernel<<<EMB / 256, 256>>>(v_b, pBQKV + 2 * EMB, EMB);
    round_f16_kernel<<<NW1 / 1024, 256>>>(out_w, pWO, NW1);
    round_f16_kernel<<<FFN_DIM * EMB / 1024, 256>>>(fc1_w, pW1, FFN_DIM * EMB);
    round_f16_kernel<<<EMB * FFN_DIM / 1024, 256>>>(fc2_w, pW2, EMB * FFN_DIM);
    transpose_in_kernel<<<MTOK, 256>>>(state);

    // 1. fused QKV projection (N = 3072)
    dim3 gQKV(E3 / 128, MTOK / 128);
    gemm_f16_kernel<<<gQKV, 256, GEMM_SMEM_BYTES>>>(pX0h, pWQKV, pBQKV, nullptr, nullptr, pQKVh, MTOK, E3, EMB, 0);

    // 2. attention (fp16 mma)
    dim3 gAttn(T_SEQ / 128, B_SZ * NHEADS);
    attn_mma_kernel<<<gAttn, 256, AT_SMEM_BYTES>>>(mask);

    // 3. out projection + residual(X0 exact) -> fp32
    dim3 gProj(EMB / 128, MTOK / 128);
    gemm_f16_kernel<<<gProj, 256, GEMM_SMEM_BYTES>>>(pATTNh, pWO, out_b, pX0, pY, nullptr, MTOK, EMB, EMB, 3);

    // 4. LN1 -> X1 exact + X1h fp16
    ln_kernel<<<MTOK, 256>>>(pY, ln1_g, ln1_b, pX1, pX1h, 0);

    // 5. fc1 + relu -> fp16 H
    dim3 gFc1(FFN_DIM / 128, MTOK / 128);
    gemm_f16_kernel<<<gFc1, 256, GEMM_SMEM_BYTES>>>(pX1h, pW1, fc1_b, nullptr, nullptr, pHh, MTOK, FFN_DIM, EMB, 2);

    // 6. fc2 + residual(X1 exact) -> fp32
    gemm_f16_kernel<<<gProj, 256, GEMM_SMEM_BYTES>>>(pHh, pW2, fc2_b, pX1, pY, nullptr, MTOK, EMB, FFN_DIM, 3);

    // 7. LN2 -> output (T,B,E)
    ln_kernel<<<MTOK, 256>>>(pY, ln2_g, ln2_b, out, nullptr, 1);
}

// round 9
// speedup vs baseline: 7.4239x; 1.1985x over previous
#include <cuda_runtime.h>
#include <cuda_fp16.h>
#include <math.h>
#include <stdint.h>

// Problem constants
#define T_SEQ 2048
#define B_SZ  4
#define EMB   1024
#define NHEADS 16
#define HD    64
#define FFN_DIM 4096
#define MTOK  (T_SEQ * B_SZ)   // 8192 tokens
#define E3    (3 * EMB)

// ---------------- scratch (device globals; no cudaMalloc allowed) ----------
__device__ float  g_X0 [MTOK * EMB];      // exact token-major input (residual)
__device__ float  g_Y  [MTOK * EMB];      // pre-LN sum
__device__ float  g_X1 [MTOK * EMB];      // exact LN1 out (residual)
__device__ __half g_X0h[MTOK * EMB];      // fp16 GEMM operands
__device__ __half g_QKVh[MTOK * E3];      // fused QKV output [tok][3*EMB]
__device__ __half g_ATTNh[MTOK * EMB];
__device__ __half g_X1h[MTOK * EMB];
__device__ __half g_Hh [MTOK * FFN_DIM];
// fp16 weights
__device__ __half g_WQKVh[E3 * EMB];      // rows: q, k, v
__device__ float  g_BQKV [E3];
__device__ __half g_WOh[EMB * EMB];
__device__ __half g_W1h[FFN_DIM * EMB];
__device__ __half g_W2h[EMB * FFN_DIM];

// ---------------------------------------------------------------------------
__device__ __forceinline__ uint32_t smem_u32(const void* p) {
    uint32_t a;
    asm("{ .reg .u64 t; cvta.to.shared.u64 t, %1; cvt.u32.u64 %0, t; }" : "=r"(a) : "l"(p));
    return a;
}
__device__ __forceinline__ void mma_f16(float* d, const uint32_t* a, const uint32_t* b) {
    asm volatile(
        "mma.sync.aligned.m16n8k16.row.col.f32.f16.f16.f32 "
        "{%0,%1,%2,%3}, {%4,%5,%6,%7}, {%8,%9}, {%0,%1,%2,%3};"
        : "+f"(d[0]), "+f"(d[1]), "+f"(d[2]), "+f"(d[3])
        : "r"(a[0]), "r"(a[1]), "r"(a[2]), "r"(a[3]), "r"(b[0]), "r"(b[1]));
}
__device__ __forceinline__ void ldmx4t(uint32_t& r0, uint32_t& r1, uint32_t& r2, uint32_t& r3,
                                       uint32_t a) {
    asm volatile("ldmatrix.sync.aligned.m8n8.x4.trans.shared.b16 {%0,%1,%2,%3}, [%4];"
                 : "=r"(r0), "=r"(r1), "=r"(r2), "=r"(r3) : "r"(a));
}
__device__ __forceinline__ void cp_async16(uint32_t dst, const void* src) {
    asm volatile("cp.async.cg.shared.global [%0], [%1], 16;" :: "r"(dst), "l"(src));
}
__device__ __forceinline__ void cp_commit() { asm volatile("cp.async.commit_group;"); }

// ---------------------------------------------------------------------------
// Round ALL weights fp32 -> fp16 in one launch (range-partitioned).
// Layout: [0,3NW1) -> WQKV (q,k,v), [3NW1,4NW1) -> WO, [4NW1,8NW1) -> W1, [8NW1,12NW1) -> W2
// ---------------------------------------------------------------------------
#define NW1 (EMB * EMB)
__global__ __launch_bounds__(256) void round_all_kernel(
    const float* __restrict__ q_w, const float* __restrict__ k_w,
    const float* __restrict__ v_w, const float* __restrict__ out_w,
    const float* __restrict__ fc1_w, const float* __restrict__ fc2_w)
{
    int i = (blockIdx.x * 256 + threadIdx.x) * 4;
    const float* src;
    __half* dst;
    int off;
    if (i < 3 * NW1) {
        dst = g_WQKVh + i;
        if (i < NW1)          { src = q_w; off = i; }
        else if (i < 2 * NW1) { src = k_w; off = i - NW1; }
        else                  { src = v_w; off = i - 2 * NW1; }
    } else if (i < 4 * NW1) { dst = g_WOh + (i - 3 * NW1); src = out_w; off = i - 3 * NW1; }
    else if (i < 8 * NW1)   { dst = g_W1h + (i - 4 * NW1); src = fc1_w; off = i - 4 * NW1; }
    else                    { dst = g_W2h + (i - 8 * NW1); src = fc2_w; off = i - 8 * NW1; }
    float4 v = *(const float4*)(src + off);
    __half2 h01 = __floats2half2_rn(v.x, v.y);
    __half2 h23 = __floats2half2_rn(v.z, v.w);
    uint2 u;
    u.x = *(uint32_t*)&h01;
    u.y = *(uint32_t*)&h23;
    *(uint2*)dst = u;
}
__global__ __launch_bounds__(256) void qkv_bias_kernel(
    const float* __restrict__ qb, const float* __restrict__ kb, const float* __restrict__ vb)
{
    int i = blockIdx.x * 256 + threadIdx.x;   // 0..3071
    const float* s = (i < EMB) ? qb : (i < 2 * EMB) ? kb : vb;
    g_BQKV[i] = s[i & (EMB - 1)];
}

// ---------------------------------------------------------------------------
// fp16 tensor-core GEMM (mma.sync m16n8k16), 2-stage cp.async. (unchanged R7)
// ---------------------------------------------------------------------------
#define GPAD 36
#define STG_OP_UINTS (128 * GPAD)
#define STG_UINTS    (2 * STG_OP_UINTS)
#define GEMM_SMEM_BYTES (2 * STG_UINTS * 4)   // 73728

__global__ __launch_bounds__(256, 2) void gemm_f16_kernel(
    const __half* __restrict__ A, const __half* __restrict__ W,
    const float* __restrict__ bias, const float* __restrict__ res,
    float* __restrict__ Cf, __half* __restrict__ Ch,
    int M, int N, int K, int mode)
{
    extern __shared__ uint32_t smg[];
    const uint32_t sbase = smem_u32(smg);

    const int tid = threadIdx.x;
    const int wid = tid >> 5;
    const int lane = tid & 31;
    const int g   = lane >> 2;
    const int tig = lane & 3;
    const int wm = wid >> 2;
    const int wn = wid & 3;
    const int m0 = blockIdx.y * 128;
    const int n0 = blockIdx.x * 128;

    const __half* Ap = A + (size_t)m0 * K;
    const __half* Wp = W + (size_t)n0 * K;

    float acc[4][4][4];
#pragma unroll
    for (int mt = 0; mt < 4; mt++)
#pragma unroll
        for (int nt = 0; nt < 4; nt++)
#pragma unroll
            for (int e = 0; e < 4; e++) acc[mt][nt][e] = 0.f;

    const int S = K >> 6;

    auto issue_stage = [&](int s) {
        const int buf = s & 1;
        const int k0h = s << 6;
        const uint32_t abase = sbase + (uint32_t)(buf * STG_UINTS) * 4;
        const uint32_t bbase = abase + STG_OP_UINTS * 4;
#pragma unroll
        for (int i = 0; i < 4; i++) {
            int idx = tid + 256 * i;
            int row = idx >> 3, cu = (idx & 7) << 2;
            cp_async16(abase + (uint32_t)(row * GPAD + cu) * 4,
                       Ap + (size_t)row * K + k0h + cu * 2);
            cp_async16(bbase + (uint32_t)(row * GPAD + cu) * 4,
                       Wp + (size_t)row * K + k0h + cu * 2);
        }
        cp_commit();
    };

    issue_stage(0);
    issue_stage(1);

    for (int s = 0; s < S; s++) {
        asm volatile("cp.async.wait_group 1;" ::: "memory");
        __syncthreads();

        const int buf = s & 1;
        const uint32_t* Ab = smg + buf * STG_UINTS + (wm * 64) * GPAD;
        const uint32_t* Bb = smg + buf * STG_UINTS + STG_OP_UINTS + (wn * 32) * GPAD;
#pragma unroll
        for (int ks = 0; ks < 4; ks++) {
            uint32_t bf[4][2];
#pragma unroll
            for (int nt = 0; nt < 4; nt++) {
                const uint32_t* bp = Bb + (nt * 8 + g) * GPAD + ks * 8 + tig;
                bf[nt][0] = bp[0];
                bf[nt][1] = bp[4];
            }
#pragma unroll
            for (int mt = 0; mt < 4; mt++) {
                uint32_t af[4];
                const uint32_t* ap = Ab + (mt * 16 + g) * GPAD + ks * 8 + tig;
                af[0] = ap[0];
                af[1] = ap[8 * GPAD];
                af[2] = ap[4];
                af[3] = ap[8 * GPAD + 4];
#pragma unroll
                for (int nt = 0; nt < 4; nt++)
                    mma_f16(acc[mt][nt], af, bf[nt]);
            }
        }
        __syncthreads();
        if (s + 2 < S) issue_stage(s + 2);
        else cp_commit();
    }

#pragma unroll
    for (int mt = 0; mt < 4; mt++) {
        int r0 = m0 + wm * 64 + mt * 16 + g;
#pragma unroll
        for (int half = 0; half < 2; half++) {
            int m = r0 + half * 8;
#pragma unroll
            for (int nt = 0; nt < 4; nt++) {
                int n = wn * 32 + nt * 8 + tig * 2;
                float ox = acc[mt][nt][half * 2 + 0] + bias[n0 + n + 0];
                float oy = acc[mt][nt][half * 2 + 1] + bias[n0 + n + 1];
                if (mode == 3) {
                    const float* Rrow = res + (size_t)m * N + n0;
                    float2 rr = *(const float2*)(Rrow + n);
                    *(float2*)(Cf + (size_t)m * N + n0 + n) = make_float2(ox + rr.x, oy + rr.y);
                } else {
                    if (mode == 2) { ox = fmaxf(ox, 0.f); oy = fmaxf(oy, 0.f); }
                    *(__half2*)(Ch + (size_t)m * N + n0 + n) = __floats2half2_rn(ox, oy);
                }
            }
        }
    }
}

// ---------------------------------------------------------------------------
// Transpose (T,B,E) -> (B,T,E): exact fp32 + fp16 copy
// ---------------------------------------------------------------------------
__global__ __launch_bounds__(256) void transpose_in_kernel(const float* __restrict__ state)
{
    int m = blockIdx.x;
    int b = m / T_SEQ;
    int t = m % T_SEQ;
    float4 v = ((const float4*)(state + (size_t)t * B_SZ * EMB + (size_t)b * EMB))[threadIdx.x];
    ((float4*)(g_X0 + (size_t)m * EMB))[threadIdx.x] = v;
    __half2 h01 = __floats2half2_rn(v.x, v.y);
    __half2 h23 = __floats2half2_rn(v.z, v.w);
    uint2 u;
    u.x = *(uint32_t*)&h01;
    u.y = *(uint32_t*)&h23;
    ((uint2*)(g_X0h + (size_t)m * EMB))[threadIdx.x] = u;
}

// ---------------------------------------------------------------------------
// Flash attention, fp16 mma, register-resident P, ldmatrix.trans V,
// cp.async double-buffered K/V.
//   grid (T/128, B*H), 256 thr = 8 warps; warp w owns q-rows w*16..+15.
// SMEM uints: Qs[128][36], 2 stages of (Ks[64][36] + Vs[64][36])
// ---------------------------------------------------------------------------
#define APADU 36
#define AT_STAGE_UINTS (2 * 64 * APADU)      // K + V per stage
#define AT_SMEM_BYTES ((128 * APADU + 2 * AT_STAGE_UINTS) * 4)   // 55296

__global__ __launch_bounds__(256, 2) void attn_mma_kernel(const uint8_t* __restrict__ mask)
{
    extern __shared__ uint32_t sma[];
    uint32_t* Qs = sma;
    const uint32_t sbase = smem_u32(sma);

    const int tq = blockIdx.x * 128;
    const int b = blockIdx.y >> 4;
    const int h = blockIdx.y & 15;
    const int tid = threadIdx.x;
    const int w = tid >> 5;
    const int lane = tid & 31;
    const int g = lane >> 2;
    const int tig = lane & 3;

    // fill Q tile
    {
        const __half* Qg = g_QKVh + (size_t)(b * T_SEQ + tq) * E3 + h * HD;
        for (int it = tid; it < 128 * 16; it += 256) {
            int r = it >> 4, c4 = (it & 15) * 4;
            uint2 raw = *(const uint2*)(Qg + (size_t)r * E3 + c4);
            *(uint2*)(Qs + r * APADU + (c4 >> 1)) = raw;
        }
    }

    const __half* KgBase = g_QKVh + (size_t)(b * T_SEQ) * E3 + EMB + h * HD;
    const __half* VgBase = g_QKVh + (size_t)(b * T_SEQ) * E3 + 2 * EMB + h * HD;

    auto issue_kv = [&](int s) {
        const int buf = s & 1;
        const int kt = s << 6;
        const uint32_t kbase = sbase + (uint32_t)(128 * APADU + buf * AT_STAGE_UINTS) * 4;
        const uint32_t vbase = kbase + (uint32_t)(64 * APADU) * 4;
#pragma unroll
        for (int i = 0; i < 4; i++) {
            int idx = tid + 256 * i;          // 0..1023
            int row = (idx >> 3) & 63;
            int chunk = idx & 7;
            int isV = idx >> 9;
            const __half* src = (isV ? VgBase : KgBase) + (size_t)(kt + row) * E3 + chunk * 8;
            uint32_t dst = (isV ? vbase : kbase) + (uint32_t)(row * APADU + chunk * 4) * 4;
            cp_async16(dst, src);
        }
        cp_commit();
    };

    issue_kv(0);
    issue_kv(1);
    __syncthreads();   // Qs visible

    // hoist Q fragments: 4 k16-steps over d=64
    uint32_t qf[4][4];
    {
        const uint32_t* base = Qs + (w * 16 + g) * APADU;
#pragma unroll
        for (int ks = 0; ks < 4; ks++) {
            qf[ks][0] = base[ks * 8 + tig];
            qf[ks][1] = base[8 * APADU + ks * 8 + tig];
            qf[ks][2] = base[ks * 8 + tig + 4];
            qf[ks][3] = base[8 * APADU + ks * 8 + tig + 4];
        }
    }

    float oacc[8][4];
#pragma unroll
    for (int nt = 0; nt < 8; nt++)
#pragma unroll
        for (int e = 0; e < 4; e++) oacc[nt][e] = 0.f;
    float mrow[2] = { -1e30f, -1e30f };
    float lrow[2] = { 0.f, 0.f };

    const uint8_t* mb = mask + (size_t)b * T_SEQ;
    const int NBLK = T_SEQ / 64;

    // ldmatrix lane address components (within V stage buffer)
    const int lm_quad = lane >> 3, lm_r = lane & 7;
    const int lm_row = (lm_quad & 1) * 8 + lm_r;      // + ks*16
    const int lm_d   = (lm_quad >> 1) * 8;            // + np*16

    for (int s = 0; s < NBLK; s++) {
        asm volatile("cp.async.wait_group 1;" ::: "memory");
        __syncthreads();

        const int buf = s & 1;
        const int kt = s << 6;
        const uint32_t* Ksb = sma + 128 * APADU + buf * AT_STAGE_UINTS;
        const uint32_t vsb_addr = sbase + (uint32_t)(128 * APADU + buf * AT_STAGE_UINTS + 64 * APADU) * 4;

        // S = Q K^T : warp computes 16 x 64
        float sacc[8][4];
#pragma unroll
        for (int nt = 0; nt < 8; nt++)
#pragma unroll
            for (int e = 0; e < 4; e++) sacc[nt][e] = 0.f;

#pragma unroll
        for (int ks = 0; ks < 4; ks++) {
#pragma unroll
            for (int nt = 0; nt < 8; nt++) {
                uint32_t bf[2];
                const uint32_t* kp = Ksb + (nt * 8 + g) * APADU + ks * 8 + tig;
                bf[0] = kp[0];
                bf[1] = kp[4];
                mma_f16(sacc[nt], qf[ks], bf);
            }
        }

        // scale + mask
#pragma unroll
        for (int nt = 0; nt < 8; nt++) {
            bool m0 = mb[kt + nt * 8 + 2 * tig] != 0;
            bool m1 = mb[kt + nt * 8 + 2 * tig + 1] != 0;
            sacc[nt][0] = m0 ? -1e30f : sacc[nt][0] * 0.125f;
            sacc[nt][1] = m1 ? -1e30f : sacc[nt][1] * 0.125f;
            sacc[nt][2] = m0 ? -1e30f : sacc[nt][2] * 0.125f;
            sacc[nt][3] = m1 ? -1e30f : sacc[nt][3] * 0.125f;
        }

        // online softmax; pack P into sacc[nt][2*half] as half2 bits (register-resident P)
#pragma unroll
        for (int half = 0; half < 2; half++) {
            float mx = -1e30f;
#pragma unroll
            for (int nt = 0; nt < 8; nt++) {
                mx = fmaxf(mx, sacc[nt][2 * half + 0]);
                mx = fmaxf(mx, sacc[nt][2 * half + 1]);
            }
            mx = fmaxf(mx, __shfl_xor_sync(0xffffffffu, mx, 1));
            mx = fmaxf(mx, __shfl_xor_sync(0xffffffffu, mx, 2));
            float mn = fmaxf(mrow[half], mx);
            float alpha = __expf(mrow[half] - mn);
            mrow[half] = mn;
            float rs = 0.f;
#pragma unroll
            for (int nt = 0; nt < 8; nt++) {
                float p0 = __expf(sacc[nt][2 * half + 0] - mn);
                float p1 = __expf(sacc[nt][2 * half + 1] - mn);
                rs += p0 + p1;
                __half2 ph = __floats2half2_rn(p0, p1);
                sacc[nt][2 * half] = __uint_as_float(*(uint32_t*)&ph);
            }
            rs += __shfl_xor_sync(0xffffffffu, rs, 1);
            rs += __shfl_xor_sync(0xffffffffu, rs, 2);
            lrow[half] = lrow[half] * alpha + rs;
#pragma unroll
            for (int nt = 0; nt < 8; nt++) {
                oacc[nt][2 * half + 0] *= alpha;
                oacc[nt][2 * half + 1] *= alpha;
            }
        }

        // O += P V : P from registers, V fragments via ldmatrix.x4.trans
#pragma unroll
        for (int ks = 0; ks < 4; ks++) {
            uint32_t af[4];
            af[0] = __float_as_uint(sacc[2 * ks + 0][0]);
            af[1] = __float_as_uint(sacc[2 * ks + 0][2]);
            af[2] = __float_as_uint(sacc[2 * ks + 1][0]);
            af[3] = __float_as_uint(sacc[2 * ks + 1][2]);
#pragma unroll
            for (int np = 0; np < 4; np++) {
                int row = ks * 16 + lm_row;
                int d   = np * 16 + lm_d;
                uint32_t addr = vsb_addr + (uint32_t)(row * APADU + (d >> 1)) * 4;
                uint32_t r0, r1, r2, r3;
                ldmx4t(r0, r1, r2, r3, addr);
                uint32_t b0[2] = { r0, r1 };
                uint32_t b1[2] = { r2, r3 };
                mma_f16(oacc[2 * np + 0], af, b0);
                mma_f16(oacc[2 * np + 1], af, b1);
            }
        }

        __syncthreads();
        if (s + 2 < NBLK) issue_kv(s + 2);
        else cp_commit();
    }

    // write fp16 output
#pragma unroll
    for (int half = 0; half < 2; half++) {
        float inv = 1.f / lrow[half];
        int r = tq + w * 16 + g + half * 8;
        __half* dst = g_ATTNh + (size_t)(b * T_SEQ + r) * EMB + h * HD;
#pragma unroll
        for (int nt = 0; nt < 8; nt++) {
            *(__half2*)(dst + nt * 8 + 2 * tig) =
                __floats2half2_rn(oacc[nt][2 * half + 0] * inv,
                                  oacc[nt][2 * half + 1] * inv);
        }
    }
}

// ---------------------------------------------------------------------------
// LayerNorm (E=1024). Optionally writes an fp16 copy.
// ---------------------------------------------------------------------------
__global__ __launch_bounds__(256) void ln_kernel(
    const float* __restrict__ X, const float* __restrict__ gw,
    const float* __restrict__ bw, float* __restrict__ out,
    __half* __restrict__ out_h, int transposed)
{
    int m = blockIdx.x;
    float4 v = ((const float4*)(X + (size_t)m * EMB))[threadIdx.x];
    float s = v.x + v.y + v.z + v.w;
    float sq = v.x * v.x + v.y * v.y + v.z * v.z + v.w * v.w;

    __shared__ float rs[256], rq[256];
    rs[threadIdx.x] = s; rq[threadIdx.x] = sq;
    __syncthreads();
    for (int st = 128; st > 0; st >>= 1) {
        if (threadIdx.x < st) {
            rs[threadIdx.x] += rs[threadIdx.x + st];
            rq[threadIdx.x] += rq[threadIdx.x + st];
        }
        __syncthreads();
    }
    float mu  = rs[0] * (1.f / EMB);
    float var = rq[0] * (1.f / EMB) - mu * mu;
    float inv = rsqrtf(var + 1e-5f);

    float4 g4 = ((const float4*)gw)[threadIdx.x];
    float4 b4 = ((const float4*)bw)[threadIdx.x];
    float4 o;
    o.x = (v.x - mu) * inv * g4.x + b4.x;
    o.y = (v.y - mu) * inv * g4.y + b4.y;
    o.z = (v.z - mu) * inv * g4.z + b4.z;
    o.w = (v.w - mu) * inv * g4.w + b4.w;

    size_t obase;
    if (transposed) {
        int b = m / T_SEQ, t = m % T_SEQ;
        obase = (size_t)t * B_SZ * EMB + (size_t)b * EMB;
    } else {
        obase = (size_t)m * EMB;
    }
    ((float4*)(out + obase))[threadIdx.x] = o;
    if (out_h) {
        __half2 h01 = __floats2half2_rn(o.x, o.y);
        __half2 h23 = __floats2half2_rn(o.z, o.w);
        uint2 u;
        u.x = *(uint32_t*)&h01;
        u.y = *(uint32_t*)&h23;
        ((uint2*)(out_h + (size_t)m * EMB))[threadIdx.x] = u;
    }
}

// ---------------------------------------------------------------------------
extern "C" void kernel_launch(void* const* d_in, const int* in_sizes, int n_in,
                              void* d_out, int out_size)
{
    const float*   state = (const float*)d_in[0];
    const uint8_t* mask  = (const uint8_t*)d_in[1];
    const float* q_w  = (const float*)d_in[2];
    const float* q_b  = (const float*)d_in[3];
    const float* k_w  = (const float*)d_in[4];
    const float* k_b  = (const float*)d_in[5];
    const float* v_w  = (const float*)d_in[6];
    const float* v_b  = (const float*)d_in[7];
    const float* out_w = (const float*)d_in[8];
    const float* out_b = (const float*)d_in[9];
    const float* ln1_g = (const float*)d_in[10];
    const float* ln1_b = (const float*)d_in[11];
    const float* fc1_w = (const float*)d_in[12];
    const float* fc1_b = (const float*)d_in[13];
    const float* fc2_w = (const float*)d_in[14];
    const float* fc2_b = (const float*)d_in[15];
    const float* ln2_g = (const float*)d_in[16];
    const float* ln2_b = (const float*)d_in[17];
    float* out = (float*)d_out;

    float *pX0, *pY, *pX1, *pBQKV;
    __half *pX0h, *pQKVh, *pATTNh, *pX1h, *pHh;
    __half *pWQKV, *pWO, *pW1, *pW2;
    cudaGetSymbolAddress((void**)&pX0,    g_X0);
    cudaGetSymbolAddress((void**)&pY,     g_Y);
    cudaGetSymbolAddress((void**)&pX1,    g_X1);
    cudaGetSymbolAddress((void**)&pX0h,   g_X0h);
    cudaGetSymbolAddress((void**)&pQKVh,  g_QKVh);
    cudaGetSymbolAddress((void**)&pATTNh, g_ATTNh);
    cudaGetSymbolAddress((void**)&pX1h,   g_X1h);
    cudaGetSymbolAddress((void**)&pHh,    g_Hh);
    cudaGetSymbolAddress((void**)&pWQKV,  g_WQKVh);
    cudaGetSymbolAddress((void**)&pBQKV,  g_BQKV);
    cudaGetSymbolAddress((void**)&pWO,    g_WOh);
    cudaGetSymbolAddress((void**)&pW1,    g_W1h);
    cudaGetSymbolAddress((void**)&pW2,    g_W2h);

    cudaFuncSetAttribute(attn_mma_kernel, cudaFuncAttributeMaxDynamicSharedMemorySize,
                         AT_SMEM_BYTES);
    cudaFuncSetAttribute(gemm_f16_kernel, cudaFuncAttributeMaxDynamicSharedMemorySize,
                         GEMM_SMEM_BYTES);

    // 0. prologue: one weight-round kernel + one bias kernel + transpose
    round_all_kernel<<<12 * NW1 / 1024, 256>>>(q_w, k_w, v_w, out_w, fc1_w, fc2_w);
    qkv_bias_kernel<<<E3 / 256, 256>>>(q_b, k_b, v_b);
    transpose_in_kernel<<<MTOK, 256>>>(state);

    // 1. fused QKV projection (N = 3072)
    dim3 gQKV(E3 / 128, MTOK / 128);
    gemm_f16_kernel<<<gQKV, 256, GEMM_SMEM_BYTES>>>(pX0h, pWQKV, pBQKV, nullptr, nullptr, pQKVh, MTOK, E3, EMB, 0);

    // 2. attention
    dim3 gAttn(T_SEQ / 128, B_SZ * NHEADS);
    attn_mma_kernel<<<gAttn, 256, AT_SMEM_BYTES>>>(mask);

    // 3. out projection + residual(X0 exact) -> fp32
    dim3 gProj(EMB / 128, MTOK / 128);
    gemm_f16_kernel<<<gProj, 256, GEMM_SMEM_BYTES>>>(pATTNh, pWO, out_b, pX0, pY, nullptr, MTOK, EMB, EMB, 3);

    // 4. LN1 -> X1 exact + X1h fp16
    ln_kernel<<<MTOK, 256>>>(pY, ln1_g, ln1_b, pX1, pX1h, 0);

    // 5. fc1 + relu -> fp16 H
    dim3 gFc1(FFN_DIM / 128, MTOK / 128);
    gemm_f16_kernel<<<gFc1, 256, GEMM_SMEM_BYTES>>>(pX1h, pW1, fc1_b, nullptr, nullptr, pHh, MTOK, FFN_DIM, EMB, 2);

    // 6. fc2 + residual(X1 exact) -> fp32
    gemm_f16_kernel<<<gProj, 256, GEMM_SMEM_BYTES>>>(pHh, pW2, fc2_b, pX1, pY, nullptr, MTOK, EMB, FFN_DIM, 3);

    // 7. LN2 -> output (T,B,E)
    ln_kernel<<<MTOK, 256>>>(pY, ln2_g, ln2_b, out, nullptr, 1);
}